// round 2
// baseline (speedup 1.0000x reference)
#include <cuda_runtime.h>
#include <cstdint>

#define NNODES 20000
#define NEDGES 320000
#define DM 128
#define PREDL 24

// ---------------- scratch (device globals; no allocation allowed) -------------
__device__ float g_h[NNODES * DM];           // node state  (10.2 MB)
__device__ float g_e[(size_t)NEDGES * DM];   // edge state  (164 MB)
__device__ float g_agg[NNODES * DM];         // scatter-sum (10.2 MB)
__device__ float g_cnt[NNODES];              // in-degree

// ---------------- packed f32x2 helpers ---------------------------------------
__device__ __forceinline__ unsigned long long pack2(float x, float y) {
    unsigned long long r;
    asm("mov.b64 %0, {%1, %2};" : "=l"(r) : "f"(x), "f"(y));
    return r;
}
__device__ __forceinline__ void fma2(unsigned long long& a, unsigned long long x,
                                     unsigned long long y) {
    asm("fma.rn.f32x2 %0, %1, %2, %0;" : "+l"(a) : "l"(x), "l"(y));
}

union Acc { unsigned long long u[16]; float f[32]; };

// ---------------- shared tiled GEMM core --------------------------------------
// C[64,128] = A^T-stored-input[K][65-strided, 64 rows] @ W[K,128] + bias
// 256 threads: tx=tid&15 -> cols c0=tx*8 ; ty=tid>>4 -> rows r0=ty*4
// Columns packed in pairs for fma.rn.f32x2 (2x fp32 throughput on sm_103a).
__device__ __forceinline__ void gemm_tile(
    const float* __restrict__ W, const float* __restrict__ bias, int K,
    const float* __restrict__ sIn, float* __restrict__ sB, Acc& A,
    int tid, int c0, int r0)
{
#pragma unroll
    for (int p = 0; p < 4; p++) {
        unsigned long long bp = pack2(bias[c0 + 2 * p], bias[c0 + 2 * p + 1]);
        A.u[p] = bp; A.u[4 + p] = bp; A.u[8 + p] = bp; A.u[12 + p] = bp;
    }
    for (int kc = 0; kc < K; kc += 32) {
        // stage 32x128 W chunk (16 KB) into smem
        const float4* Wv = (const float4*)(W + kc * 128);
        float4* sBv = (float4*)sB;
#pragma unroll
        for (int i = 0; i < 4; i++) sBv[tid + i * 256] = Wv[tid + i * 256];
        __syncthreads();
#pragma unroll 8
        for (int kk = 0; kk < 32; kk++) {
            const float* ar = sIn + (kc + kk) * 65 + r0;
            unsigned long long a0 = pack2(ar[0], ar[0]);
            unsigned long long a1 = pack2(ar[1], ar[1]);
            unsigned long long a2 = pack2(ar[2], ar[2]);
            unsigned long long a3 = pack2(ar[3], ar[3]);
            const unsigned long long* br =
                (const unsigned long long*)(sB + kk * 128 + c0);
            unsigned long long b0 = br[0], b1 = br[1], b2 = br[2], b3 = br[3];
            fma2(A.u[0],  a0, b0); fma2(A.u[1],  a0, b1);
            fma2(A.u[2],  a0, b2); fma2(A.u[3],  a0, b3);
            fma2(A.u[4],  a1, b0); fma2(A.u[5],  a1, b1);
            fma2(A.u[6],  a1, b2); fma2(A.u[7],  a1, b3);
            fma2(A.u[8],  a2, b0); fma2(A.u[9],  a2, b1);
            fma2(A.u[10], a2, b2); fma2(A.u[11], a2, b3);
            fma2(A.u[12], a3, b0); fma2(A.u[13], a3, b1);
            fma2(A.u[14], a3, b2); fma2(A.u[15], a3, b3);
        }
        __syncthreads();
    }
}

__device__ __forceinline__ float gelu_tanh(float x) {
    // JAX default gelu: approximate=True (tanh form)
    float x3 = x * x * x;
    float t = tanhf(0.7978845608028654f * (x + 0.044715f * x3));
    return 0.5f * x * (1.0f + t);
}

// gelu + LayerNorm(gamma,beta) over the 128-wide row, 16-lane shuffle reduce
__device__ __forceinline__ void gelu_ln(Acc& A, const float* __restrict__ gg,
                                        const float* __restrict__ bb, int c0)
{
    float gv[8], bv[8];
#pragma unroll
    for (int j = 0; j < 8; j++) { gv[j] = gg[c0 + j]; bv[j] = bb[c0 + j]; }
#pragma unroll
    for (int i = 0; i < 32; i++) A.f[i] = gelu_tanh(A.f[i]);
#pragma unroll
    for (int r = 0; r < 4; r++) {
        float s = 0.f, q = 0.f;
#pragma unroll
        for (int j = 0; j < 8; j++) { float v = A.f[r * 8 + j]; s += v; q += v * v; }
#pragma unroll
        for (int o = 1; o < 16; o <<= 1) {
            s += __shfl_xor_sync(0xffffffffu, s, o);
            q += __shfl_xor_sync(0xffffffffu, q, o);
        }
        float m  = s * (1.0f / 128.0f);
        float vr = q * (1.0f / 128.0f) - m * m;
        float rs = rsqrtf(vr + 1e-5f);
#pragma unroll
        for (int j = 0; j < 8; j++)
            A.f[r * 8 + j] = (A.f[r * 8 + j] - m) * rs * gv[j] + bv[j];
    }
}

__device__ __forceinline__ void store_T(float* __restrict__ s, const float* acc,
                                        int c0, int r0)
{
#pragma unroll
    for (int j = 0; j < 8; j++)
#pragma unroll
        for (int r = 0; r < 4; r++)
            s[(c0 + j) * 65 + r0 + r] = acc[r * 8 + j];
}

// ---------------- kernels -----------------------------------------------------

// h = nodes.reshape(N,288) @ W + b
__global__ __launch_bounds__(256, 1) void emb_node_kernel(
    const float* __restrict__ nodes, const float* __restrict__ W,
    const float* __restrict__ bias, float* __restrict__ h)
{
    extern __shared__ float sm[];
    float* sAT = sm;              // 288*65
    float* sB  = sAT + 288 * 65; // 4096
    int tid = threadIdx.x;
    int base = blockIdx.x * 64;
    for (int i = tid; i < 64 * 72; i += 256) {
        int row = i / 72, c4 = i % 72;
        int n = min(base + row, NNODES - 1);
        float4 v = *(const float4*)(nodes + n * 288 + c4 * 4);
        float* d = sAT + (c4 * 4) * 65 + row;
        d[0] = v.x; d[65] = v.y; d[130] = v.z; d[195] = v.w;
    }
    __syncthreads();
    int tx = tid & 15, ty = tid >> 4, c0 = tx * 8, r0 = ty * 4;
    Acc A;
    gemm_tile(W, bias, 288, sAT, sB, A, tid, c0, r0);
#pragma unroll
    for (int r = 0; r < 4; r++) {
        int n = base + r0 + r;
        if (n < NNODES) {
            float* hp = h + n * DM + c0;
            *(float4*)hp       = *(float4*)&A.f[r * 8];
            *(float4*)(hp + 4) = *(float4*)&A.f[r * 8 + 4];
        }
    }
}

// e = edges(E,2) @ W(2,128) + b  (elementwise, K=2)
__global__ void emb_edge_kernel(const float* __restrict__ edges,
                                const float* __restrict__ W,
                                const float* __restrict__ bias,
                                float* __restrict__ e)
{
    int idx = blockIdx.x * 256 + threadIdx.x;   // E*32 float4 units
    if (idx >= NEDGES * 32) return;
    int ei = idx >> 5, c4 = idx & 31;
    float x0 = edges[2 * ei], x1 = edges[2 * ei + 1];
    float4 w0 = *(const float4*)(W + c4 * 4);
    float4 w1 = *(const float4*)(W + DM + c4 * 4);
    float4 b  = *(const float4*)(bias + c4 * 4);
    float4 o;
    o.x = fmaf(x0, w0.x, fmaf(x1, w1.x, b.x));
    o.y = fmaf(x0, w0.y, fmaf(x1, w1.y, b.y));
    o.z = fmaf(x0, w0.z, fmaf(x1, w1.z, b.z));
    o.w = fmaf(x0, w0.w, fmaf(x1, w1.w, b.w));
    *(float4*)(e + (size_t)ei * DM + c4 * 4) = o;
}

__global__ void count_kernel(const int* __restrict__ receivers,
                             float* __restrict__ cnt)
{
    int i = blockIdx.x * 256 + threadIdx.x;
    if (i < NEDGES) atomicAdd(&cnt[receivers[i]], 1.0f);
}

// fused edge update: e += MLP(concat(e,h[s],h[r]) @ Wp + bp); agg += e_new
__global__ __launch_bounds__(256, 1) void edge_kernel(
    const float* __restrict__ h, float* __restrict__ e,
    const int* __restrict__ senders, const int* __restrict__ receivers,
    const float* __restrict__ Wp, const float* __restrict__ bp,
    const float* __restrict__ W0, const float* __restrict__ b0,
    const float* __restrict__ g0, const float* __restrict__ be0,
    const float* __restrict__ W1, const float* __restrict__ b1,
    const float* __restrict__ g1, const float* __restrict__ be1,
    float* __restrict__ agg)
{
    extern __shared__ float sm[];
    float* sAT = sm;               // 384*65 (transposed A: cols 0..127=e, ..=h[s], ..=h[r])
    float* sX  = sAT + 384 * 65;  // 128*65 intermediate
    float* sB  = sX + 128 * 65;   // 4096 W chunk
    int* sSnd  = (int*)(sB + 4096);
    int* sRcv  = sSnd + 64;
    int tid = threadIdx.x;
    int base = blockIdx.x * 64;
    if (tid < 64)       sSnd[tid]      = senders[base + tid];
    else if (tid < 128) sRcv[tid - 64] = receivers[base + tid - 64];
    __syncthreads();
    for (int i = tid; i < 64 * 96; i += 256) {
        int row = i / 96, c4 = i % 96;
        const float* src;
        if (c4 < 32)      src = e + (size_t)(base + row) * DM + c4 * 4;
        else if (c4 < 64) src = h + (size_t)sSnd[row] * DM + (c4 - 32) * 4;
        else              src = h + (size_t)sRcv[row] * DM + (c4 - 64) * 4;
        float4 v = *(const float4*)src;
        float* d = sAT + (c4 * 4) * 65 + row;
        d[0] = v.x; d[65] = v.y; d[130] = v.z; d[195] = v.w;
    }
    __syncthreads();
    int tx = tid & 15, ty = tid >> 4, c0 = tx * 8, r0 = ty * 4;
    Acc A;
    gemm_tile(Wp, bp, 384, sAT, sB, A, tid, c0, r0);   // projection (no act)
    store_T(sX, A.f, c0, r0);
    gemm_tile(W0, b0, 128, sX, sB, A, tid, c0, r0);    // mlp layer 0
    gelu_ln(A, g0, be0, c0);
    store_T(sX, A.f, c0, r0);
    gemm_tile(W1, b1, 128, sX, sB, A, tid, c0, r0);    // mlp layer 1
    gelu_ln(A, g1, be1, c0);
#pragma unroll
    for (int r = 0; r < 4; r++) {
        int row = r0 + r;
#pragma unroll
        for (int j = 0; j < 8; j++)
            A.f[r * 8 + j] += sAT[(c0 + j) * 65 + row];  // residual (e cols intact)
        float* ep = e + (size_t)(base + row) * DM + c0;
        *(float4*)ep       = *(float4*)&A.f[r * 8];
        *(float4*)(ep + 4) = *(float4*)&A.f[r * 8 + 4];
        float* ag = agg + (size_t)sRcv[row] * DM + c0;
#pragma unroll
        for (int j = 0; j < 8; j++) atomicAdd(ag + j, A.f[r * 8 + j]);
    }
}

// fused node update: h += MLP(concat(h, agg/cnt) @ Wp + bp)
__global__ __launch_bounds__(256, 1) void node_kernel(
    float* __restrict__ h, const float* __restrict__ agg,
    const float* __restrict__ cnt,
    const float* __restrict__ Wp, const float* __restrict__ bp,
    const float* __restrict__ W0, const float* __restrict__ b0,
    const float* __restrict__ g0, const float* __restrict__ be0,
    const float* __restrict__ W1, const float* __restrict__ b1,
    const float* __restrict__ g1, const float* __restrict__ be1)
{
    extern __shared__ float sm[];
    float* sAT  = sm;               // 256*65
    float* sX   = sAT + 256 * 65;  // 128*65
    float* sB   = sX + 128 * 65;   // 4096
    float* sInv = sB + 4096;       // 64
    int tid = threadIdx.x;
    int base = blockIdx.x * 64;
    if (tid < 64) {
        int n = min(base + tid, NNODES - 1);
        sInv[tid] = 1.0f / fmaxf(cnt[n], 1.0f);
    }
    __syncthreads();
    for (int i = tid; i < 64 * 64; i += 256) {
        int row = i / 64, c4 = i % 64;
        int n = min(base + row, NNODES - 1);
        float4 v;
        if (c4 < 32) v = *(const float4*)(h + n * DM + c4 * 4);
        else {
            v = *(const float4*)(agg + n * DM + (c4 - 32) * 4);
            float iv = sInv[row];
            v.x *= iv; v.y *= iv; v.z *= iv; v.w *= iv;
        }
        float* d = sAT + (c4 * 4) * 65 + row;
        d[0] = v.x; d[65] = v.y; d[130] = v.z; d[195] = v.w;
    }
    __syncthreads();
    int tx = tid & 15, ty = tid >> 4, c0 = tx * 8, r0 = ty * 4;
    Acc A;
    gemm_tile(Wp, bp, 256, sAT, sB, A, tid, c0, r0);
    store_T(sX, A.f, c0, r0);
    gemm_tile(W0, b0, 128, sX, sB, A, tid, c0, r0);
    gelu_ln(A, g0, be0, c0);
    store_T(sX, A.f, c0, r0);
    gemm_tile(W1, b1, 128, sX, sB, A, tid, c0, r0);
    gelu_ln(A, g1, be1, c0);
#pragma unroll
    for (int r = 0; r < 4; r++) {
        int row = r0 + r;
        int n = base + row;
#pragma unroll
        for (int j = 0; j < 8; j++)
            A.f[r * 8 + j] += sAT[(c0 + j) * 65 + row];   // residual h
        if (n < NNODES) {
            float* hp = h + n * DM + c0;
            *(float4*)hp       = *(float4*)&A.f[r * 8];
            *(float4*)(hp + 4) = *(float4*)&A.f[r * 8 + 4];
        }
    }
}

// out = LN(gelu(h @ Wout + b)) @ proj_w + proj_b
__global__ __launch_bounds__(256, 1) void out_kernel(
    const float* __restrict__ h,
    const float* __restrict__ W, const float* __restrict__ bias,
    const float* __restrict__ gg, const float* __restrict__ bb,
    const float* __restrict__ pw, const float* __restrict__ pb,
    float* __restrict__ out)
{
    extern __shared__ float sm[];
    float* sAT = sm;               // 128*65
    float* sB  = sAT + 128 * 65;  // 4096
    float* sT  = sB + 4096;       // 64*129 (row-major LN output)
    int tid = threadIdx.x;
    int base = blockIdx.x * 64;
    for (int i = tid; i < 64 * 32; i += 256) {
        int row = i / 32, c4 = i % 32;
        int n = min(base + row, NNODES - 1);
        float4 v = *(const float4*)(h + n * DM + c4 * 4);
        float* d = sAT + (c4 * 4) * 65 + row;
        d[0] = v.x; d[65] = v.y; d[130] = v.z; d[195] = v.w;
    }
    __syncthreads();
    int tx = tid & 15, ty = tid >> 4, c0 = tx * 8, r0 = ty * 4;
    Acc A;
    gemm_tile(W, bias, 128, sAT, sB, A, tid, c0, r0);
    gelu_ln(A, gg, bb, c0);
#pragma unroll
    for (int r = 0; r < 4; r++)
#pragma unroll
        for (int j = 0; j < 8; j++)
            sT[(r0 + r) * 129 + c0 + j] = A.f[r * 8 + j];
    __syncthreads();
    for (int i = tid; i < 64 * PREDL; i += 256) {
        int row = i / PREDL, oc = i % PREDL;
        int n = base + row;
        if (n < NNODES) {
            float s = pb[oc];
            const float* tr = sT + row * 129;
#pragma unroll 8
            for (int k = 0; k < 128; k++) s = fmaf(tr[k], pw[k * PREDL + oc], s);
            out[n * PREDL + oc] = s;
        }
    }
}

// ---------------- launch ------------------------------------------------------
extern "C" void kernel_launch(void* const* d_in, const int* in_sizes, int n_in,
                              void* d_out, int out_size)
{
    const float* nodes        = (const float*)d_in[0];
    const float* edges        = (const float*)d_in[1];
    const int*   senders      = (const int*)d_in[2];
    const int*   receivers    = (const int*)d_in[3];
    const float* w_node_emb   = (const float*)d_in[4];
    const float* b_node_emb   = (const float*)d_in[5];
    const float* w_edge_emb   = (const float*)d_in[6];
    const float* b_edge_emb   = (const float*)d_in[7];
    const float* edge_proj_w  = (const float*)d_in[8];
    const float* edge_proj_b  = (const float*)d_in[9];
    const float* node_proj_w  = (const float*)d_in[10];
    const float* node_proj_b  = (const float*)d_in[11];
    const float* edge_mlp_w   = (const float*)d_in[12];
    const float* edge_mlp_b   = (const float*)d_in[13];
    const float* edge_ln_g    = (const float*)d_in[14];
    const float* edge_ln_b    = (const float*)d_in[15];
    const float* node_mlp_w   = (const float*)d_in[16];
    const float* node_mlp_b   = (const float*)d_in[17];
    const float* node_ln_g    = (const float*)d_in[18];
    const float* node_ln_b    = (const float*)d_in[19];
    const float* mlp_out_w    = (const float*)d_in[20];
    const float* mlp_out_b    = (const float*)d_in[21];
    const float* mlp_out_g    = (const float*)d_in[22];
    const float* mlp_out_beta = (const float*)d_in[23];
    const float* proj_w       = (const float*)d_in[24];
    const float* proj_b       = (const float*)d_in[25];
    float* out = (float*)d_out;

    float *h, *e, *agg, *cnt;
    cudaGetSymbolAddress((void**)&h,   g_h);
    cudaGetSymbolAddress((void**)&e,   g_e);
    cudaGetSymbolAddress((void**)&agg, g_agg);
    cudaGetSymbolAddress((void**)&cnt, g_cnt);

    int smem_edge = (384 * 65 + 128 * 65 + 4096 + 128) * 4;
    int smem_node = (256 * 65 + 128 * 65 + 4096 + 64) * 4;
    int smem_emb  = (288 * 65 + 4096) * 4;
    int smem_out  = (128 * 65 + 4096 + 64 * 129) * 4;
    cudaFuncSetAttribute(edge_kernel,     cudaFuncAttributeMaxDynamicSharedMemorySize, smem_edge);
    cudaFuncSetAttribute(node_kernel,     cudaFuncAttributeMaxDynamicSharedMemorySize, smem_node);
    cudaFuncSetAttribute(emb_node_kernel, cudaFuncAttributeMaxDynamicSharedMemorySize, smem_emb);
    cudaFuncSetAttribute(out_kernel,      cudaFuncAttributeMaxDynamicSharedMemorySize, smem_out);

    int nblk = (NNODES + 63) / 64;  // 313

    cudaMemsetAsync(cnt, 0, NNODES * sizeof(float));
    emb_node_kernel<<<nblk, 256, smem_emb>>>(nodes, w_node_emb, b_node_emb, h);
    emb_edge_kernel<<<NEDGES * 32 / 256, 256>>>(edges, w_edge_emb, b_edge_emb, e);
    count_kernel<<<(NEDGES + 255) / 256, 256>>>(receivers, cnt);

    for (int l = 0; l < 2; l++) {
        cudaMemsetAsync(agg, 0, (size_t)NNODES * DM * sizeof(float));
        edge_kernel<<<NEDGES / 64, 256, smem_edge>>>(
            h, e, senders, receivers,
            edge_proj_w + l * 384 * 128, edge_proj_b + l * 128,
            edge_mlp_w + (l * 2 + 0) * 128 * 128, edge_mlp_b + (l * 2 + 0) * 128,
            edge_ln_g + (l * 2 + 0) * 128, edge_ln_b + (l * 2 + 0) * 128,
            edge_mlp_w + (l * 2 + 1) * 128 * 128, edge_mlp_b + (l * 2 + 1) * 128,
            edge_ln_g + (l * 2 + 1) * 128, edge_ln_b + (l * 2 + 1) * 128,
            agg);
        node_kernel<<<nblk, 256, smem_node>>>(
            h, agg, cnt,
            node_proj_w + l * 256 * 128, node_proj_b + l * 128,
            node_mlp_w + (l * 2 + 0) * 128 * 128, node_mlp_b + (l * 2 + 0) * 128,
            node_ln_g + (l * 2 + 0) * 128, node_ln_b + (l * 2 + 0) * 128,
            node_mlp_w + (l * 2 + 1) * 128 * 128, node_mlp_b + (l * 2 + 1) * 128,
            node_ln_g + (l * 2 + 1) * 128, node_ln_b + (l * 2 + 1) * 128);
    }
    out_kernel<<<nblk, 256, smem_out>>>(h, mlp_out_w, mlp_out_b, mlp_out_g,
                                        mlp_out_beta, proj_w, proj_b, out);
}

// round 4
// speedup vs baseline: 2.5998x; 2.5998x over previous
#include <cuda_runtime.h>
#include <cstdint>

#define NNODES 20000
#define NEDGES 320000
#define DM 128
#define PREDL 24

#define STA 132              // A_T / X_T / E_T stride (floats)
#define STW 133              // W tile stride (floats)
#define CHA (32 * STA)       // A chunk floats
#define CHW (32 * STW)       // W chunk floats

// smem float offsets
#define F_IDX  0             // 256 ints (snd/rcv) or 128 inv floats
#define F_SUM  256
#define F_SQ   512
#define F_PAR  768           // up to 896 floats of per-col params
#define F_SW   1664          // 2 * CHW = 8512
#define F_SG   10176         // 2 * CHA = 8448
#define F_ET   18624         // 128*132 persistent residual tile
#define F_XT   35520         // 128*132 activation tile
#define SMEMB  (52416 * 4)   // 209664 bytes

// ---------------- device scratch ----------------------------------------------
__device__ float g_h[NNODES * DM];
__device__ float g_e[(size_t)NEDGES * DM];
__device__ float g_agg[NNODES * DM];
__device__ float g_cnt[NNODES];

// ---------------- helpers ------------------------------------------------------
__device__ __forceinline__ uint32_t tfr(float x) {
    uint32_t r;
    asm("cvt.rna.tf32.f32 %0, %1;" : "=r"(r) : "f"(x));
    return r;
}
__device__ __forceinline__ float tff(float x) { return __uint_as_float(tfr(x)); }

__device__ __forceinline__ void mma8(float c[4], uint32_t a0, uint32_t a1,
                                     uint32_t a2, uint32_t a3,
                                     uint32_t b0, uint32_t b1) {
    asm volatile(
        "mma.sync.aligned.m16n8k8.row.col.f32.tf32.tf32.f32 "
        "{%0,%1,%2,%3}, {%4,%5,%6,%7}, {%8,%9}, {%0,%1,%2,%3};"
        : "+f"(c[0]), "+f"(c[1]), "+f"(c[2]), "+f"(c[3])
        : "r"(a0), "r"(a1), "r"(a2), "r"(a3), "r"(b0), "r"(b1));
}

__device__ __forceinline__ float geluf(float x) {
    float x3 = x * x * x;
    return 0.5f * x * (1.0f + tanhf(0.7978845608028654f * (x + 0.044715f * x3)));
}

// one 32-wide K chunk of the 128x128 tile GEMM
__device__ __forceinline__ void chunk_mma(const float* __restrict__ sA,
                                          const float* __restrict__ sW,
                                          float C[2][8][4],
                                          int wm, int wn, int g, int tig) {
#pragma unroll
    for (int kk = 0; kk < 4; kk++) {
        const float* w0 = sW + (kk * 8 + tig) * STW + wn * 64 + g;
        const float* w1 = w0 + 4 * STW;
        uint32_t b0[8], b1[8];
#pragma unroll
        for (int nt = 0; nt < 8; nt++) {
            b0[nt] = __float_as_uint(w0[nt * 8]);
            b1[nt] = __float_as_uint(w1[nt * 8]);
        }
        const float* ap = sA + (kk * 8 + tig) * STA + wm * 32 + g;
#pragma unroll
        for (int mm = 0; mm < 2; mm++) {
            uint32_t a0 = __float_as_uint(ap[mm * 16]);
            uint32_t a1 = __float_as_uint(ap[mm * 16 + 8]);
            uint32_t a2 = __float_as_uint(ap[4 * STA + mm * 16]);
            uint32_t a3 = __float_as_uint(ap[4 * STA + mm * 16 + 8]);
#pragma unroll
            for (int nt = 0; nt < 8; nt++)
                mma8(C[mm][nt], a0, a1, a2, a3, b0[nt], b1[nt]);
        }
    }
}

// stage a [32][128] W chunk (row-major in gmem) into sw (stride 133), tf32-rounded
__device__ __forceinline__ void stage_W(float* sw, const float* __restrict__ gw,
                                        int tid) {
    int k = tid >> 3, s16 = (tid & 7) * 16;
    const float4* src = (const float4*)(gw + k * 128 + s16);
    float* d = sw + k * STW + s16;
#pragma unroll
    for (int j = 0; j < 4; j++) {
        float4 v = src[j];
        d[j * 4 + 0] = tff(v.x); d[j * 4 + 1] = tff(v.y);
        d[j * 4 + 2] = tff(v.z); d[j * 4 + 3] = tff(v.w);
    }
}

// stage 16 floats of a gathered row into transposed A chunk (stride 132)
__device__ __forceinline__ void stage_A(float* sg, const float* __restrict__ src32,
                                        int r, int hh) {
    const float4* s4 = (const float4*)(src32 + hh * 16);
    float* d = sg + (hh * 16) * STA + r;
#pragma unroll
    for (int j = 0; j < 4; j++) {
        float4 v = s4[j];
        d[(j * 4 + 0) * STA] = tff(v.x); d[(j * 4 + 1) * STA] = tff(v.y);
        d[(j * 4 + 2) * STA] = tff(v.z); d[(j * 4 + 3) * STA] = tff(v.w);
    }
}
__device__ __forceinline__ void stage_As(float* sg, const float* __restrict__ src32,
                                         int r, int hh, float sc) {
    const float4* s4 = (const float4*)(src32 + hh * 16);
    float* d = sg + (hh * 16) * STA + r;
#pragma unroll
    for (int j = 0; j < 4; j++) {
        float4 v = s4[j];
        d[(j * 4 + 0) * STA] = tff(v.x * sc); d[(j * 4 + 1) * STA] = tff(v.y * sc);
        d[(j * 4 + 2) * STA] = tff(v.z * sc); d[(j * 4 + 3) * STA] = tff(v.w * sc);
    }
}

// stage a full 128-col fp32 row tile into transposed layout (residual-exact)
__device__ __forceinline__ void stage_T128(float* dstT, const float* __restrict__ row,
                                           int r, int hh) {
    const float4* s4 = (const float4*)(row + hh * 64);
    float* ET = dstT;
#pragma unroll
    for (int i = 0; i < 16; i++) {
        float4 v = s4[i];
        float* d = ET + (hh * 64 + i * 4) * STA + r;
        d[0] = v.x; d[STA] = v.y; d[2 * STA] = v.z; d[3 * STA] = v.w;
    }
}

// gelu + LayerNorm epilogue on accumulator fragments
__device__ __forceinline__ void gelu_ln_ep(float C[2][8][4], float* smf,
                                           int wm, int wn, int g, int tig,
                                           int pb, int pg, int pbe) {
    float* sSum = smf + F_SUM;
    float* sSq  = smf + F_SQ;
#pragma unroll
    for (int mm = 0; mm < 2; mm++)
#pragma unroll
        for (int h = 0; h < 2; h++) {
            float ps = 0.f, pq = 0.f;
#pragma unroll
            for (int nt = 0; nt < 8; nt++)
#pragma unroll
                for (int s = 0; s < 2; s++) {
                    int col = wn * 64 + nt * 8 + tig * 2 + s;
                    float v = geluf(C[mm][nt][h * 2 + s] + smf[pb + col]);
                    C[mm][nt][h * 2 + s] = v;
                    ps += v; pq += v * v;
                }
            ps += __shfl_xor_sync(0xffffffffu, ps, 1);
            ps += __shfl_xor_sync(0xffffffffu, ps, 2);
            pq += __shfl_xor_sync(0xffffffffu, pq, 1);
            pq += __shfl_xor_sync(0xffffffffu, pq, 2);
            if (tig == 0) {
                int row = wm * 32 + mm * 16 + h * 8 + g;
                sSum[row * 2 + wn] = ps;
                sSq[row * 2 + wn]  = pq;
            }
        }
    __syncthreads();
#pragma unroll
    for (int mm = 0; mm < 2; mm++)
#pragma unroll
        for (int h = 0; h < 2; h++) {
            int row = wm * 32 + mm * 16 + h * 8 + g;
            float m = (sSum[row * 2] + sSum[row * 2 + 1]) * (1.0f / 128.0f);
            float q = (sSq[row * 2] + sSq[row * 2 + 1]) * (1.0f / 128.0f);
            float rs = rsqrtf(q - m * m + 1e-5f);
#pragma unroll
            for (int nt = 0; nt < 8; nt++)
#pragma unroll
                for (int s = 0; s < 2; s++) {
                    int col = wn * 64 + nt * 8 + tig * 2 + s;
                    C[mm][nt][h * 2 + s] =
                        (C[mm][nt][h * 2 + s] - m) * rs * smf[pg + col] + smf[pbe + col];
                }
        }
}

__device__ __forceinline__ void write_XT(float C[2][8][4], float* XT,
                                         int wm, int wn, int g, int tig, int cvt) {
#pragma unroll
    for (int mm = 0; mm < 2; mm++)
#pragma unroll
        for (int h = 0; h < 2; h++) {
            int row = wm * 32 + mm * 16 + h * 8 + g;
#pragma unroll
            for (int nt = 0; nt < 8; nt++)
#pragma unroll
                for (int s = 0; s < 2; s++) {
                    int col = wn * 64 + nt * 8 + tig * 2 + s;
                    float v = C[mm][nt][h * 2 + s];
                    XT[col * STA + row] = cvt ? tff(v) : v;
                }
        }
}

#define ZERO_C() do { \
    _Pragma("unroll") for (int _m = 0; _m < 2; _m++) \
    _Pragma("unroll") for (int _n = 0; _n < 8; _n++) \
    _Pragma("unroll") for (int _s = 0; _s < 4; _s++) C[_m][_n][_s] = 0.f; } while (0)

// run a K=128 GEMM with A = XT chunks, W streamed (4 chunks)
__device__ __forceinline__ void gemm_from_XT(float* smf, const float* __restrict__ W,
                                             float C[2][8][4], int tid,
                                             int wm, int wn, int g, int tig) {
    stage_W(smf + F_SW, W, tid);
    __syncthreads();
    for (int c = 0; c < 4; c++) {
        if (c < 3) stage_W(smf + F_SW + ((c + 1) & 1) * CHW, W + (c + 1) * 4096, tid);
        chunk_mma(smf + F_XT + c * CHA, smf + F_SW + (c & 1) * CHW, C, wm, wn, g, tig);
        __syncthreads();
    }
}

// ---------------- edge kernel --------------------------------------------------
__global__ __launch_bounds__(256, 1) void edge_k(
    const float* __restrict__ h, float* __restrict__ e,
    const int* __restrict__ snd, const int* __restrict__ rcv,
    const float* __restrict__ wP, const float* __restrict__ bp,
    const float* __restrict__ wM0, const float* __restrict__ b0,
    const float* __restrict__ g0, const float* __restrict__ be0,
    const float* __restrict__ wM1, const float* __restrict__ b1,
    const float* __restrict__ g1, const float* __restrict__ be1,
    float* __restrict__ agg)
{
    extern __shared__ float smf[];
    int tid = threadIdx.x, lane = tid & 31, wid = tid >> 5;
    int wm = wid & 3, wn = wid >> 2, g = lane >> 2, tig = lane & 3;
    int base = blockIdx.x * 128;
    int r = tid >> 1, hh = tid & 1;
    int* sI = (int*)smf;
    if (tid < 128) sI[tid] = snd[base + tid];
    else           sI[tid] = rcv[base + tid - 128];
    if (tid < 128) {
        float* p = smf + F_PAR;
        p[tid] = bp[tid];        p[128 + tid] = b0[tid];
        p[256 + tid] = g0[tid];  p[384 + tid] = be0[tid];
        p[512 + tid] = b1[tid];  p[640 + tid] = g1[tid];
        p[768 + tid] = be1[tid];
    }
    stage_T128(smf + F_ET, e + (size_t)(base + r) * DM, r, hh);

    float C[2][8][4];
    ZERO_C();
    // GEMM1: K=384 (chunks 0-3 = e tile, 4-7 = h[snd], 8-11 = h[rcv])
    stage_W(smf + F_SW, wP, tid);
    __syncthreads();
    for (int c = 0; c < 12; c++) {
        if (c < 11) {
            int cn = c + 1;
            stage_W(smf + F_SW + (cn & 1) * CHW, wP + cn * 4096, tid);
            if (cn >= 4) {
                int idx = sI[(cn < 8 ? 0 : 128) + r];
                stage_A(smf + F_SG + (cn & 1) * CHA,
                        h + (size_t)idx * DM + (cn & 3) * 32, r, hh);
            }
        }
        const float* As = (c < 4) ? smf + F_ET + c * CHA
                                  : smf + F_SG + (c & 1) * CHA;
        chunk_mma(As, smf + F_SW + (c & 1) * CHW, C, wm, wn, g, tig);
        __syncthreads();
    }
    // ep1: +bias, to XT
#pragma unroll
    for (int mm = 0; mm < 2; mm++)
#pragma unroll
        for (int hx = 0; hx < 2; hx++) {
            int row = wm * 32 + mm * 16 + hx * 8 + g;
#pragma unroll
            for (int nt = 0; nt < 8; nt++)
#pragma unroll
                for (int s = 0; s < 2; s++) {
                    int col = wn * 64 + nt * 8 + tig * 2 + s;
                    smf[F_XT + col * STA + row] =
                        tff(C[mm][nt][hx * 2 + s] + smf[F_PAR + col]);
                }
        }
    __syncthreads();

    ZERO_C();
    gemm_from_XT(smf, wM0, C, tid, wm, wn, g, tig);
    gelu_ln_ep(C, smf, wm, wn, g, tig, F_PAR + 128, F_PAR + 256, F_PAR + 384);
    write_XT(C, smf + F_XT, wm, wn, g, tig, 1);
    __syncthreads();

    ZERO_C();
    gemm_from_XT(smf, wM1, C, tid, wm, wn, g, tig);
    gelu_ln_ep(C, smf, wm, wn, g, tig, F_PAR + 512, F_PAR + 640, F_PAR + 768);

    // residual + store + scatter
#pragma unroll
    for (int mm = 0; mm < 2; mm++)
#pragma unroll
        for (int hx = 0; hx < 2; hx++) {
            int row = wm * 32 + mm * 16 + hx * 8 + g;
            int rc = sI[128 + row];
            float* eo = e + (size_t)(base + row) * DM;
            float* ag = agg + (size_t)rc * DM;
#pragma unroll
            for (int nt = 0; nt < 8; nt++) {
                int col0 = wn * 64 + nt * 8 + tig * 2;
                float v0 = C[mm][nt][hx * 2 + 0] + smf[F_ET + col0 * STA + row];
                float v1 = C[mm][nt][hx * 2 + 1] + smf[F_ET + (col0 + 1) * STA + row];
                *(float2*)(eo + col0) = make_float2(v0, v1);
                atomicAdd(ag + col0, v0);
                atomicAdd(ag + col0 + 1, v1);
            }
        }
}

// ---------------- node kernel --------------------------------------------------
__global__ __launch_bounds__(256, 1) void node_k(
    float* __restrict__ h, const float* __restrict__ agg,
    const float* __restrict__ cnt,
    const float* __restrict__ wP, const float* __restrict__ bp,
    const float* __restrict__ wM0, const float* __restrict__ b0,
    const float* __restrict__ g0, const float* __restrict__ be0,
    const float* __restrict__ wM1, const float* __restrict__ b1,
    const float* __restrict__ g1, const float* __restrict__ be1)
{
    extern __shared__ float smf[];
    int tid = threadIdx.x, lane = tid & 31, wid = tid >> 5;
    int wm = wid & 3, wn = wid >> 2, g = lane >> 2, tig = lane & 3;
    int base = blockIdx.x * 128;
    int r = tid >> 1, hh = tid & 1;
    if (tid < 128) {
        int n = min(base + tid, NNODES - 1);
        smf[tid] = 1.0f / fmaxf(cnt[n], 1.0f);
        float* p = smf + F_PAR;
        p[tid] = bp[tid];        p[128 + tid] = b0[tid];
        p[256 + tid] = g0[tid];  p[384 + tid] = be0[tid];
        p[512 + tid] = b1[tid];  p[640 + tid] = g1[tid];
        p[768 + tid] = be1[tid];
    }
    int nr = min(base + r, NNODES - 1);
    stage_T128(smf + F_ET, h + (size_t)nr * DM, r, hh);
    __syncthreads();                         // inv visible before gathers

    float C[2][8][4];
    ZERO_C();
    stage_W(smf + F_SW, wP, tid);
    __syncthreads();
    for (int c = 0; c < 8; c++) {
        if (c < 7) {
            int cn = c + 1;
            stage_W(smf + F_SW + (cn & 1) * CHW, wP + cn * 4096, tid);
            if (cn >= 4)
                stage_As(smf + F_SG + (cn & 1) * CHA,
                         agg + (size_t)nr * DM + (cn & 3) * 32, r, hh, smf[r]);
        }
        const float* As = (c < 4) ? smf + F_ET + c * CHA
                                  : smf + F_SG + (c & 1) * CHA;
        chunk_mma(As, smf + F_SW + (c & 1) * CHW, C, wm, wn, g, tig);
        __syncthreads();
    }
#pragma unroll
    for (int mm = 0; mm < 2; mm++)
#pragma unroll
        for (int hx = 0; hx < 2; hx++) {
            int row = wm * 32 + mm * 16 + hx * 8 + g;
#pragma unroll
            for (int nt = 0; nt < 8; nt++)
#pragma unroll
                for (int s = 0; s < 2; s++) {
                    int col = wn * 64 + nt * 8 + tig * 2 + s;
                    smf[F_XT + col * STA + row] =
                        tff(C[mm][nt][hx * 2 + s] + smf[F_PAR + col]);
                }
        }
    __syncthreads();

    ZERO_C();
    gemm_from_XT(smf, wM0, C, tid, wm, wn, g, tig);
    gelu_ln_ep(C, smf, wm, wn, g, tig, F_PAR + 128, F_PAR + 256, F_PAR + 384);
    write_XT(C, smf + F_XT, wm, wn, g, tig, 1);
    __syncthreads();

    ZERO_C();
    gemm_from_XT(smf, wM1, C, tid, wm, wn, g, tig);
    gelu_ln_ep(C, smf, wm, wn, g, tig, F_PAR + 512, F_PAR + 640, F_PAR + 768);

#pragma unroll
    for (int mm = 0; mm < 2; mm++)
#pragma unroll
        for (int hx = 0; hx < 2; hx++) {
            int row = wm * 32 + mm * 16 + hx * 8 + g;
            if (base + row >= NNODES) continue;
            float* ho = h + (size_t)(base + row) * DM;
#pragma unroll
            for (int nt = 0; nt < 8; nt++) {
                int col0 = wn * 64 + nt * 8 + tig * 2;
                float v0 = C[mm][nt][hx * 2 + 0] + smf[F_ET + col0 * STA + row];
                float v1 = C[mm][nt][hx * 2 + 1] + smf[F_ET + (col0 + 1) * STA + row];
                *(float2*)(ho + col0) = make_float2(v0, v1);
            }
        }
}

// ---------------- node embedding ----------------------------------------------
__global__ __launch_bounds__(256, 1) void emb_k(
    const float* __restrict__ nodes, const float* __restrict__ wE,
    const float* __restrict__ bias, float* __restrict__ h)
{
    extern __shared__ float smf[];
    int tid = threadIdx.x, lane = tid & 31, wid = tid >> 5;
    int wm = wid & 3, wn = wid >> 2, g = lane >> 2, tig = lane & 3;
    int base = blockIdx.x * 128;
    int r = tid >> 1, hh = tid & 1;
    if (tid < 128) smf[F_PAR + tid] = bias[tid];
    int nr = min(base + r, NNODES - 1);
    const float* src = nodes + (size_t)nr * 288;

    float C[2][8][4];
    ZERO_C();
    stage_W(smf + F_SW, wE, tid);
    stage_A(smf + F_SG, src, r, hh);
    __syncthreads();
    for (int c = 0; c < 9; c++) {
        if (c < 8) {
            int cn = c + 1;
            stage_W(smf + F_SW + (cn & 1) * CHW, wE + cn * 4096, tid);
            stage_A(smf + F_SG + (cn & 1) * CHA, src + cn * 32, r, hh);
        }
        chunk_mma(smf + F_SG + (c & 1) * CHA, smf + F_SW + (c & 1) * CHW,
                  C, wm, wn, g, tig);
        __syncthreads();
    }
#pragma unroll
    for (int mm = 0; mm < 2; mm++)
#pragma unroll
        for (int hx = 0; hx < 2; hx++) {
            int row = wm * 32 + mm * 16 + hx * 8 + g;
            if (base + row >= NNODES) continue;
            float* ho = h + (size_t)(base + row) * DM;
#pragma unroll
            for (int nt = 0; nt < 8; nt++) {
                int col0 = wn * 64 + nt * 8 + tig * 2;
                float v0 = C[mm][nt][hx * 2 + 0] + smf[F_PAR + col0];
                float v1 = C[mm][nt][hx * 2 + 1] + smf[F_PAR + col0 + 1];
                *(float2*)(ho + col0) = make_float2(v0, v1);
            }
        }
}

// ---------------- output kernel ------------------------------------------------
__global__ __launch_bounds__(256, 1) void out_k(
    const float* __restrict__ h, const float* __restrict__ wO,
    const float* __restrict__ bias, const float* __restrict__ gg,
    const float* __restrict__ bb, const float* __restrict__ pw,
    const float* __restrict__ pb, float* __restrict__ out)
{
    extern __shared__ float smf[];
    int tid = threadIdx.x, lane = tid & 31, wid = tid >> 5;
    int wm = wid & 3, wn = wid >> 2, g = lane >> 2, tig = lane & 3;
    int base = blockIdx.x * 128;
    int r = tid >> 1, hh = tid & 1;
    if (tid < 128) {
        smf[F_PAR + tid] = bias[tid];
        smf[F_PAR + 128 + tid] = gg[tid];
        smf[F_PAR + 256 + tid] = bb[tid];
    }
    int nr = min(base + r, NNODES - 1);
    const float* src = h + (size_t)nr * DM;

    float C[2][8][4];
    ZERO_C();
    stage_W(smf + F_SW, wO, tid);
    stage_A(smf + F_SG, src, r, hh);
    __syncthreads();
    for (int c = 0; c < 4; c++) {
        if (c < 3) {
            int cn = c + 1;
            stage_W(smf + F_SW + (cn & 1) * CHW, wO + cn * 4096, tid);
            stage_A(smf + F_SG + (cn & 1) * CHA, src + cn * 32, r, hh);
        }
        chunk_mma(smf + F_SG + (c & 1) * CHA, smf + F_SW + (c & 1) * CHW,
                  C, wm, wn, g, tig);
        __syncthreads();
    }
    gelu_ln_ep(C, smf, wm, wn, g, tig, F_PAR, F_PAR + 128, F_PAR + 256);
    write_XT(C, smf + F_XT, wm, wn, g, tig, 0);   // exact f32
    // stage projection weights into unused E_T area
    float* sPw = smf + F_ET;
    for (int i = tid; i < 128 * PREDL; i += 256) sPw[i] = pw[i];
    if (tid < PREDL) smf[F_ET + 128 * PREDL + tid] = pb[tid];
    __syncthreads();

    if (base + r < NNODES) {
        float acc[12];
#pragma unroll
        for (int j = 0; j < 12; j++) acc[j] = smf[F_ET + 128 * PREDL + hh * 12 + j];
        for (int k = 0; k < 128; k++) {
            float xv = smf[F_XT + k * STA + r];
            const float* pr = sPw + k * PREDL + hh * 12;
#pragma unroll
            for (int j = 0; j < 12; j++) acc[j] = fmaf(xv, pr[j], acc[j]);
        }
        float* o = out + (size_t)(base + r) * PREDL + hh * 12;
#pragma unroll
        for (int j = 0; j < 12; j++) o[j] = acc[j];
    }
}

// ---------------- small kernels -------------------------------------------------
__global__ void emb_edge_kernel(const float* __restrict__ edges,
                                const float* __restrict__ W,
                                const float* __restrict__ bias,
                                float* __restrict__ e)
{
    int idx = blockIdx.x * 256 + threadIdx.x;
    if (idx >= NEDGES * 32) return;
    int ei = idx >> 5, c4 = idx & 31;
    float x0 = edges[2 * ei], x1 = edges[2 * ei + 1];
    float4 w0 = *(const float4*)(W + c4 * 4);
    float4 w1 = *(const float4*)(W + DM + c4 * 4);
    float4 b  = *(const float4*)(bias + c4 * 4);
    float4 o;
    o.x = fmaf(x0, w0.x, fmaf(x1, w1.x, b.x));
    o.y = fmaf(x0, w0.y, fmaf(x1, w1.y, b.y));
    o.z = fmaf(x0, w0.z, fmaf(x1, w1.z, b.z));
    o.w = fmaf(x0, w0.w, fmaf(x1, w1.w, b.w));
    *(float4*)(e + (size_t)ei * DM + c4 * 4) = o;
}

__global__ void count_kernel(const int* __restrict__ receivers,
                             float* __restrict__ cnt)
{
    int i = blockIdx.x * 256 + threadIdx.x;
    if (i < NEDGES) atomicAdd(&cnt[receivers[i]], 1.0f);
}

// ---------------- launch ------------------------------------------------------
extern "C" void kernel_launch(void* const* d_in, const int* in_sizes, int n_in,
                              void* d_out, int out_size)
{
    const float* nodes        = (const float*)d_in[0];
    const float* edges        = (const float*)d_in[1];
    const int*   senders      = (const int*)d_in[2];
    const int*   receivers    = (const int*)d_in[3];
    const float* w_node_emb   = (const float*)d_in[4];
    const float* b_node_emb   = (const float*)d_in[5];
    const float* w_edge_emb   = (const float*)d_in[6];
    const float* b_edge_emb   = (const float*)d_in[7];
    const float* edge_proj_w  = (const float*)d_in[8];
    const float* edge_proj_b  = (const float*)d_in[9];
    const float* node_proj_w  = (const float*)d_in[10];
    const float* node_proj_b  = (const float*)d_in[11];
    const float* edge_mlp_w   = (const float*)d_in[12];
    const float* edge_mlp_b   = (const float*)d_in[13];
    const float* edge_ln_g    = (const float*)d_in[14];
    const float* edge_ln_b    = (const float*)d_in[15];
    const float* node_mlp_w   = (const float*)d_in[16];
    const float* node_mlp_b   = (const float*)d_in[17];
    const float* node_ln_g    = (const float*)d_in[18];
    const float* node_ln_b    = (const float*)d_in[19];
    const float* mlp_out_w    = (const float*)d_in[20];
    const float* mlp_out_b    = (const float*)d_in[21];
    const float* mlp_out_g    = (const float*)d_in[22];
    const float* mlp_out_beta = (const float*)d_in[23];
    const float* proj_w       = (const float*)d_in[24];
    const float* proj_b       = (const float*)d_in[25];
    float* out = (float*)d_out;

    float *h, *e, *agg, *cnt;
    cudaGetSymbolAddress((void**)&h,   g_h);
    cudaGetSymbolAddress((void**)&e,   g_e);
    cudaGetSymbolAddress((void**)&agg, g_agg);
    cudaGetSymbolAddress((void**)&cnt, g_cnt);

    cudaFuncSetAttribute(edge_k, cudaFuncAttributeMaxDynamicSharedMemorySize, SMEMB);
    cudaFuncSetAttribute(node_k, cudaFuncAttributeMaxDynamicSharedMemorySize, SMEMB);
    cudaFuncSetAttribute(emb_k,  cudaFuncAttributeMaxDynamicSharedMemorySize, SMEMB);
    cudaFuncSetAttribute(out_k,  cudaFuncAttributeMaxDynamicSharedMemorySize, SMEMB);

    int nblk = (NNODES + 127) / 128;  // 157

    cudaMemsetAsync(cnt, 0, NNODES * sizeof(float));
    emb_k<<<nblk, 256, SMEMB>>>(nodes, w_node_emb, b_node_emb, h);
    emb_edge_kernel<<<NEDGES * 32 / 256, 256>>>(edges, w_edge_emb, b_edge_emb, e);
    count_kernel<<<(NEDGES + 255) / 256, 256>>>(receivers, cnt);

    for (int l = 0; l < 2; l++) {
        cudaMemsetAsync(agg, 0, (size_t)NNODES * DM * sizeof(float));
        edge_k<<<NEDGES / 128, 256, SMEMB>>>(
            h, e, senders, receivers,
            edge_proj_w + l * 384 * 128, edge_proj_b + l * 128,
            edge_mlp_w + (l * 2 + 0) * 128 * 128, edge_mlp_b + (l * 2 + 0) * 128,
            edge_ln_g + (l * 2 + 0) * 128, edge_ln_b + (l * 2 + 0) * 128,
            edge_mlp_w + (l * 2 + 1) * 128 * 128, edge_mlp_b + (l * 2 + 1) * 128,
            edge_ln_g + (l * 2 + 1) * 128, edge_ln_b + (l * 2 + 1) * 128,
            agg);
        node_k<<<nblk, 256, SMEMB>>>(
            h, agg, cnt,
            node_proj_w + l * 256 * 128, node_proj_b + l * 128,
            node_mlp_w + (l * 2 + 0) * 128 * 128, node_mlp_b + (l * 2 + 0) * 128,
            node_ln_g + (l * 2 + 0) * 128, node_ln_b + (l * 2 + 0) * 128,
            node_mlp_w + (l * 2 + 1) * 128 * 128, node_mlp_b + (l * 2 + 1) * 128,
            node_ln_g + (l * 2 + 1) * 128, node_ln_b + (l * 2 + 1) * 128);
    }
    out_k<<<nblk, 256, SMEMB>>>(h, mlp_out_w, mlp_out_b, mlp_out_g,
                                mlp_out_beta, proj_w, proj_b, out);
}

// round 5
// speedup vs baseline: 3.0787x; 1.1842x over previous
#include <cuda_runtime.h>
#include <cstdint>

#define NNODES 20000
#define NEDGES 320000
#define DM 128
#define PREDL 24

// ---------------- device scratch ----------------------------------------------
__device__ float g_h[NNODES * DM];
__device__ float g_e[(size_t)NEDGES * DM];
__device__ float g_agg[NNODES * DM];
__device__ float g_cnt[NNODES];
__device__ float g_wt[85 * 4096];     // fragment-layout weights (tf32-rounded)

// weight blob offsets (in 4096-float chunks)
#define C_WPE  0     // edge proj  2 x 12
#define C_WPN  24    // node proj  2 x 8
#define C_WME  40    // edge mlp   4 x 4
#define C_WMN  56    // node mlp   4 x 4
#define C_WOUT 72    // out mlp    4
#define C_WEMB 76    // node emb   9

// ---------------- smem float offsets -------------------------------------------
#define F_IDX 0                 // 256 ints (snd|rcv) or 128 inv floats
#define F_SUM 256
#define F_SQ  512
#define F_PAR 768               // up to 896 per-col params
#define F_SW  1664              // 2 x 4096 W double buffer
#define F_SG  (F_SW + 8192)     // 2 x 4096 gather double buffer
#define F_ET  (F_SG + 8192)     // 4 x 4096 persistent residual tile (exact f32)
#define F_XT  (F_ET + 16384)    // 4 x 4096 activation tile
#define SMEMB ((F_XT + 16384) * 4)   // 203264 bytes

// ---------------- helpers ------------------------------------------------------
__device__ __forceinline__ uint32_t tfr(float x) {
    uint32_t r;
    asm("cvt.rna.tf32.f32 %0, %1;" : "=r"(r) : "f"(x));
    return r;
}
__device__ __forceinline__ float tff(float x) { return __uint_as_float(tfr(x)); }

__device__ __forceinline__ void mma8(float c[4], uint32_t a0, uint32_t a1,
                                     uint32_t a2, uint32_t a3,
                                     uint32_t b0, uint32_t b1) {
    asm volatile(
        "mma.sync.aligned.m16n8k8.row.col.f32.tf32.tf32.f32 "
        "{%0,%1,%2,%3}, {%4,%5,%6,%7}, {%8,%9}, {%0,%1,%2,%3};"
        : "+f"(c[0]), "+f"(c[1]), "+f"(c[2]), "+f"(c[3])
        : "r"(a0), "r"(a1), "r"(a2), "r"(a3), "r"(b0), "r"(b1));
}

__device__ __forceinline__ float geluf(float x) {
    float x3 = x * x * x;
    return 0.5f * x * (1.0f + tanhf(0.7978845608028654f * (x + 0.044715f * x3)));
}

__device__ __forceinline__ int fAg(int g) { return (g ^ (g >> 2)) & 3; }

// A-fragment index within a 4096-float chunk, for (row 0..127, k_local 0..31)
__device__ __forceinline__ int aidx(int row, int kl) {
    int wm = row >> 5, mm = (row >> 4) & 1, r8 = (row >> 3) & 1, g = row & 7;
    int kk = kl >> 3, k4 = (kl >> 2) & 1, tig = kl & 3;
    return (((kk * 4 + wm) * 2 + mm) << 7) + ((g * 4 + (tig ^ fAg(g))) << 2)
           + r8 + (k4 << 1);
}
// B-fragment index within a chunk, for (k_local, n)
__device__ __forceinline__ int bidx(int kl, int n) {
    int kk = kl >> 3, k4 = (kl >> 2) & 1, tig = kl & 3;
    int wn = n >> 6, ntp = (n >> 4) & 3, ntb = (n >> 3) & 1, gq = n & 7;
    return (((kk * 2 + wn) * 4 + ntp) << 7) + ((gq * 4 + tig) << 2)
           + ntb * 2 + k4;
}

// one 32-wide K chunk of the 128x128 tile GEMM (frag-native, vector LDS)
__device__ __forceinline__ void chunk_mma(const float* __restrict__ sA,
                                          const float* __restrict__ sW,
                                          float C[2][8][4], int wm, int wn,
                                          int lane, int pl4) {
#pragma unroll
    for (int kk = 0; kk < 4; kk++) {
        float4 bf[4];
#pragma unroll
        for (int ntp = 0; ntp < 4; ntp++)
            bf[ntp] = *(const float4*)(sW + (((kk * 2 + wn) * 4 + ntp) << 7)
                                       + (lane << 2));
#pragma unroll
        for (int mm = 0; mm < 2; mm++) {
            float4 av = *(const float4*)(sA + (((kk * 4 + wm) * 2 + mm) << 7) + pl4);
            uint32_t a0 = __float_as_uint(av.x), a1 = __float_as_uint(av.y);
            uint32_t a2 = __float_as_uint(av.z), a3 = __float_as_uint(av.w);
#pragma unroll
            for (int ntp = 0; ntp < 4; ntp++) {
                mma8(C[mm][2 * ntp], a0, a1, a2, a3,
                     __float_as_uint(bf[ntp].x), __float_as_uint(bf[ntp].y));
                mma8(C[mm][2 * ntp + 1], a0, a1, a2, a3,
                     __float_as_uint(bf[ntp].z), __float_as_uint(bf[ntp].w));
            }
        }
    }
}

// copy one pre-fragmented 16KB W chunk (conflict-free)
__device__ __forceinline__ void copy_w(float* dst, const float* __restrict__ src,
                                       int tid) {
#pragma unroll
    for (int i = 0; i < 4; i++)
        ((float4*)dst)[tid + i * 256] = ((const float4*)src)[tid + i * 256];
}

// stage 16 gathered floats (row r, kl = hh*16..+15) into A-frag chunk, tf32
__device__ __forceinline__ void stage_Af(float* chunk, const float* __restrict__ src,
                                         int r, int hh) {
    float vv[16];
#pragma unroll
    for (int i = 0; i < 4; i++) {
        float4 v = *(const float4*)(src + i * 4);
        vv[i * 4] = v.x; vv[i * 4 + 1] = v.y; vv[i * 4 + 2] = v.z; vv[i * 4 + 3] = v.w;
    }
#pragma unroll
    for (int j = 0; j < 16; j++) chunk[aidx(r, hh * 16 + j)] = tff(vv[j]);
}
__device__ __forceinline__ void stage_Afs(float* chunk, const float* __restrict__ src,
                                          int r, int hh, float sc) {
    float vv[16];
#pragma unroll
    for (int i = 0; i < 4; i++) {
        float4 v = *(const float4*)(src + i * 4);
        vv[i * 4] = v.x * sc; vv[i * 4 + 1] = v.y * sc;
        vv[i * 4 + 2] = v.z * sc; vv[i * 4 + 3] = v.w * sc;
    }
#pragma unroll
    for (int j = 0; j < 16; j++) chunk[aidx(r, hh * 16 + j)] = tff(vv[j]);
}

// stage 64 cols (hh half) of a 128-wide row EXACT into 2 A-frag chunks
__device__ __forceinline__ void stage_E(float* ET, const float* __restrict__ rowp,
                                        int r, int hh) {
#pragma unroll
    for (int c2 = 0; c2 < 2; c2++) {
        int ch = hh * 2 + c2;
        float* chunk = ET + ch * 4096;
        const float* src = rowp + ch * 32;
#pragma unroll
        for (int i = 0; i < 8; i++) {
            float4 v = *(const float4*)(src + i * 4);
            chunk[aidx(r, i * 4)]     = v.x;
            chunk[aidx(r, i * 4 + 1)] = v.y;
            chunk[aidx(r, i * 4 + 2)] = v.z;
            chunk[aidx(r, i * 4 + 3)] = v.w;
        }
    }
}

// GEMM1 epilogue: D + bias -> XT (tf32)
__device__ __forceinline__ void ep_bias_to_XT(float C[2][8][4], float* smf,
                                              int wm, int wn, int lane, int pbias) {
    int g = lane >> 2, q = lane & 3;
#pragma unroll
    for (int mm = 0; mm < 2; mm++)
#pragma unroll
        for (int hx = 0; hx < 2; hx++) {
            int row = wm * 32 + mm * 16 + hx * 8 + g;
#pragma unroll
            for (int nt = 0; nt < 8; nt++)
#pragma unroll
                for (int s = 0; s < 2; s++) {
                    int col = wn * 64 + nt * 8 + q * 2 + s;
                    smf[F_XT + (col >> 5) * 4096 + aidx(row, col & 31)] =
                        tff(C[mm][nt][hx * 2 + s] + smf[pbias + col]);
                }
        }
}

// post-LN write to XT (cvt: 1 = tf32 round for next GEMM, 0 = exact)
__device__ __forceinline__ void write_XT(float C[2][8][4], float* smf,
                                         int wm, int wn, int lane, int cvt) {
    int g = lane >> 2, q = lane & 3;
#pragma unroll
    for (int mm = 0; mm < 2; mm++)
#pragma unroll
        for (int hx = 0; hx < 2; hx++) {
            int row = wm * 32 + mm * 16 + hx * 8 + g;
#pragma unroll
            for (int nt = 0; nt < 8; nt++)
#pragma unroll
                for (int s = 0; s < 2; s++) {
                    int col = wn * 64 + nt * 8 + q * 2 + s;
                    float v = C[mm][nt][hx * 2 + s];
                    smf[F_XT + (col >> 5) * 4096 + aidx(row, col & 31)] =
                        cvt ? tff(v) : v;
                }
        }
}

// gelu + LayerNorm over 128-wide rows (two warps per row combine via smem)
__device__ __forceinline__ void gelu_ln_ep(float C[2][8][4], float* smf,
                                           int wm, int wn, int lane,
                                           int pb, int pg, int pbe) {
    int g = lane >> 2, q = lane & 3;
    float* sSum = smf + F_SUM;
    float* sSq  = smf + F_SQ;
#pragma unroll
    for (int mm = 0; mm < 2; mm++)
#pragma unroll
        for (int hx = 0; hx < 2; hx++) {
            float ps = 0.f, pq = 0.f;
#pragma unroll
            for (int nt = 0; nt < 8; nt++)
#pragma unroll
                for (int s = 0; s < 2; s++) {
                    int col = wn * 64 + nt * 8 + q * 2 + s;
                    float v = geluf(C[mm][nt][hx * 2 + s] + smf[pb + col]);
                    C[mm][nt][hx * 2 + s] = v;
                    ps += v; pq += v * v;
                }
            ps += __shfl_xor_sync(0xffffffffu, ps, 1);
            ps += __shfl_xor_sync(0xffffffffu, ps, 2);
            pq += __shfl_xor_sync(0xffffffffu, pq, 1);
            pq += __shfl_xor_sync(0xffffffffu, pq, 2);
            if (q == 0) {
                int row = wm * 32 + mm * 16 + hx * 8 + g;
                sSum[row * 2 + wn] = ps;
                sSq[row * 2 + wn]  = pq;
            }
        }
    __syncthreads();
#pragma unroll
    for (int mm = 0; mm < 2; mm++)
#pragma unroll
        for (int hx = 0; hx < 2; hx++) {
            int row = wm * 32 + mm * 16 + hx * 8 + g;
            float m = (sSum[row * 2] + sSum[row * 2 + 1]) * (1.0f / 128.0f);
            float qv = (sSq[row * 2] + sSq[row * 2 + 1]) * (1.0f / 128.0f);
            float rs = rsqrtf(qv - m * m + 1e-5f);
#pragma unroll
            for (int nt = 0; nt < 8; nt++)
#pragma unroll
                for (int s = 0; s < 2; s++) {
                    int col = wn * 64 + nt * 8 + q * 2 + s;
                    C[mm][nt][hx * 2 + s] =
                        (C[mm][nt][hx * 2 + s] - m) * rs * smf[pg + col] + smf[pbe + col];
                }
        }
}

#define ZERO_C() do { \
    _Pragma("unroll") for (int _m = 0; _m < 2; _m++) \
    _Pragma("unroll") for (int _n = 0; _n < 8; _n++) \
    _Pragma("unroll") for (int _s = 0; _s < 4; _s++) C[_m][_n][_s] = 0.f; } while (0)

// K=128 GEMM with A = XT chunks, W streamed double-buffered
__device__ __forceinline__ void gemm_XT(float* smf, const float* __restrict__ W,
                                        float C[2][8][4], int tid,
                                        int wm, int wn, int lane, int pl4) {
    copy_w(smf + F_SW, W, tid);
    __syncthreads();
#pragma unroll 1
    for (int c = 0; c < 4; c++) {
        if (c < 3) copy_w(smf + F_SW + ((c + 1) & 1) * 4096, W + (c + 1) * 4096, tid);
        chunk_mma(smf + F_XT + c * 4096, smf + F_SW + (c & 1) * 4096,
                  C, wm, wn, lane, pl4);
        __syncthreads();
    }
}

// row-major readback precomputed base for A-frag reads
#define ROWBASE(r, rb, fg) \
    int rb = ((((r) >> 5) * 2 + (((r) >> 4) & 1)) << 7) + (((r) & 7) << 4) \
             + (((r) >> 3) & 1); \
    int fg = fAg((r) & 7)
#define AFIDX(rb, fg, j) \
    (((j) >> 3) * 1024 + (rb) + ((((j) & 3) ^ (fg)) << 2) + ((((j) >> 2) & 1) << 1))

#define RED4(p, f4) asm volatile( \
    "red.global.add.v4.f32 [%0], {%1,%2,%3,%4};" \
    :: "l"(p), "f"((f4).x), "f"((f4).y), "f"((f4).z), "f"((f4).w) : "memory")

// ---------------- weight prep: W[K,128] -> B-frag chunks (tf32) ---------------
__global__ void prep_w(const float* __restrict__ W, float* __restrict__ dst) {
    int c = blockIdx.x, tid = threadIdx.x;
    int kl = tid >> 3, n0 = (tid & 7) * 16;
#pragma unroll
    for (int j = 0; j < 16; j++) {
        int n = n0 + j;
        dst[c * 4096 + bidx(kl, n)] = tff(W[(c * 32 + kl) * 128 + n]);
    }
}

// ---------------- edge kernel --------------------------------------------------
__global__ __launch_bounds__(256, 1) void edge_k(
    const float* __restrict__ h, float* __restrict__ e,
    const int* __restrict__ snd, const int* __restrict__ rcv,
    const float* __restrict__ wP, const float* __restrict__ bp,
    const float* __restrict__ wM0, const float* __restrict__ b0,
    const float* __restrict__ g0, const float* __restrict__ be0,
    const float* __restrict__ wM1, const float* __restrict__ b1,
    const float* __restrict__ g1, const float* __restrict__ be1,
    float* __restrict__ agg)
{
    extern __shared__ float smf[];
    int tid = threadIdx.x, lane = tid & 31, wid = tid >> 5;
    int wm = wid & 3, wn = wid >> 2;
    int g = lane >> 2, tig = lane & 3;
    int pl4 = (g * 4 + (tig ^ fAg(g))) << 2;
    int base = blockIdx.x * 128;
    int r = tid >> 1, hh = tid & 1;
    int* sI = (int*)smf;
    if (tid < 128) sI[tid] = snd[base + tid];
    else           sI[tid] = rcv[base + tid - 128];
    if (tid < 128) {
        float* p = smf + F_PAR;
        p[tid] = bp[tid];        p[128 + tid] = b0[tid];
        p[256 + tid] = g0[tid];  p[384 + tid] = be0[tid];
        p[512 + tid] = b1[tid];  p[640 + tid] = g1[tid];
        p[768 + tid] = be1[tid];
    }
    stage_E(smf + F_ET, e + (size_t)(base + r) * DM, r, hh);

    float C[2][8][4];
    ZERO_C();
    // GEMM1: K=384 (chunks 0-3 = e tile (exact, HW-truncated), 4-11 gathered)
    copy_w(smf + F_SW, wP, tid);
    __syncthreads();
#pragma unroll 1
    for (int c = 0; c < 12; c++) {
        if (c < 11) {
            int cn = c + 1;
            copy_w(smf + F_SW + (cn & 1) * 4096, wP + cn * 4096, tid);
            if (cn >= 4) {
                int idx = sI[(cn < 8 ? 0 : 128) + r];
                stage_Af(smf + F_SG + (cn & 1) * 4096,
                         h + (size_t)idx * DM + ((cn & 3) << 5) + hh * 16, r, hh);
            }
        }
        const float* As = (c < 4) ? smf + F_ET + c * 4096
                                  : smf + F_SG + (c & 1) * 4096;
        chunk_mma(As, smf + F_SW + (c & 1) * 4096, C, wm, wn, lane, pl4);
        __syncthreads();
    }
    ep_bias_to_XT(C, smf, wm, wn, lane, F_PAR);
    ZERO_C();
    gemm_XT(smf, wM0, C, tid, wm, wn, lane, pl4);          // MLP layer 0
    gelu_ln_ep(C, smf, wm, wn, lane, F_PAR + 128, F_PAR + 256, F_PAR + 384);
    write_XT(C, smf, wm, wn, lane, 1);
    ZERO_C();
    gemm_XT(smf, wM1, C, tid, wm, wn, lane, pl4);          // MLP layer 1
    gelu_ln_ep(C, smf, wm, wn, lane, F_PAR + 512, F_PAR + 640, F_PAR + 768);
    write_XT(C, smf, wm, wn, lane, 0);                     // exact
    __syncthreads();

    // residual + store + vector scatter
    {
        ROWBASE(r, rb, fg);
        float* eo = e + (size_t)(base + r) * DM + hh * 64;
        float* ag = agg + (size_t)sI[128 + r] * DM + hh * 64;
#pragma unroll
        for (int c2 = 0; c2 < 2; c2++) {
            const float* X = smf + F_XT + (hh * 2 + c2) * 4096;
            const float* E = smf + F_ET + (hh * 2 + c2) * 4096;
#pragma unroll
            for (int qq = 0; qq < 8; qq++) {
                float4 f4;
                f4.x = X[AFIDX(rb, fg, qq * 4 + 0)] + E[AFIDX(rb, fg, qq * 4 + 0)];
                f4.y = X[AFIDX(rb, fg, qq * 4 + 1)] + E[AFIDX(rb, fg, qq * 4 + 1)];
                f4.z = X[AFIDX(rb, fg, qq * 4 + 2)] + E[AFIDX(rb, fg, qq * 4 + 2)];
                f4.w = X[AFIDX(rb, fg, qq * 4 + 3)] + E[AFIDX(rb, fg, qq * 4 + 3)];
                *(float4*)(eo + c2 * 32 + qq * 4) = f4;
                RED4(ag + c2 * 32 + qq * 4, f4);
            }
        }
    }
}

// ---------------- node kernel --------------------------------------------------
__global__ __launch_bounds__(256, 1) void node_k(
    float* __restrict__ h, const float* __restrict__ agg,
    const float* __restrict__ cnt,
    const float* __restrict__ wP, const float* __restrict__ bp,
    const float* __restrict__ wM0, const float* __restrict__ b0,
    const float* __restrict__ g0, const float* __restrict__ be0,
    const float* __restrict__ wM1, const float* __restrict__ b1,
    const float* __restrict__ g1, const float* __restrict__ be1)
{
    extern __shared__ float smf[];
    int tid = threadIdx.x, lane = tid & 31, wid = tid >> 5;
    int wm = wid & 3, wn = wid >> 2;
    int g = lane >> 2, tig = lane & 3;
    int pl4 = (g * 4 + (tig ^ fAg(g))) << 2;
    int base = blockIdx.x * 128;
    int r = tid >> 1, hh = tid & 1;
    if (tid < 128) {
        int n = min(base + tid, NNODES - 1);
        smf[tid] = 1.0f / fmaxf(cnt[n], 1.0f);
        float* p = smf + F_PAR;
        p[tid] = bp[tid];        p[128 + tid] = b0[tid];
        p[256 + tid] = g0[tid];  p[384 + tid] = be0[tid];
        p[512 + tid] = b1[tid];  p[640 + tid] = g1[tid];
        p[768 + tid] = be1[tid];
    }
    int nr = min(base + r, NNODES - 1);
    stage_E(smf + F_ET, h + (size_t)nr * DM, r, hh);

    float C[2][8][4];
    ZERO_C();
    copy_w(smf + F_SW, wP, tid);
    __syncthreads();
#pragma unroll 1
    for (int c = 0; c < 8; c++) {
        if (c < 7) {
            int cn = c + 1;
            copy_w(smf + F_SW + (cn & 1) * 4096, wP + cn * 4096, tid);
            if (cn >= 4)
                stage_Afs(smf + F_SG + (cn & 1) * 4096,
                          agg + (size_t)nr * DM + ((cn & 3) << 5) + hh * 16,
                          r, hh, smf[r]);
        }
        const float* As = (c < 4) ? smf + F_ET + c * 4096
                                  : smf + F_SG + (c & 1) * 4096;
        chunk_mma(As, smf + F_SW + (c & 1) * 4096, C, wm, wn, lane, pl4);
        __syncthreads();
    }
    ep_bias_to_XT(C, smf, wm, wn, lane, F_PAR);
    ZERO_C();
    gemm_XT(smf, wM0, C, tid, wm, wn, lane, pl4);
    gelu_ln_ep(C, smf, wm, wn, lane, F_PAR + 128, F_PAR + 256, F_PAR + 384);
    write_XT(C, smf, wm, wn, lane, 1);
    ZERO_C();
    gemm_XT(smf, wM1, C, tid, wm, wn, lane, pl4);
    gelu_ln_ep(C, smf, wm, wn, lane, F_PAR + 512, F_PAR + 640, F_PAR + 768);
    write_XT(C, smf, wm, wn, lane, 0);
    __syncthreads();

    if (base + r < NNODES) {
        ROWBASE(r, rb, fg);
        float* ho = h + (size_t)(base + r) * DM + hh * 64;
#pragma unroll
        for (int c2 = 0; c2 < 2; c2++) {
            const float* X = smf + F_XT + (hh * 2 + c2) * 4096;
            const float* E = smf + F_ET + (hh * 2 + c2) * 4096;
#pragma unroll
            for (int qq = 0; qq < 8; qq++) {
                float4 f4;
                f4.x = X[AFIDX(rb, fg, qq * 4 + 0)] + E[AFIDX(rb, fg, qq * 4 + 0)];
                f4.y = X[AFIDX(rb, fg, qq * 4 + 1)] + E[AFIDX(rb, fg, qq * 4 + 1)];
                f4.z = X[AFIDX(rb, fg, qq * 4 + 2)] + E[AFIDX(rb, fg, qq * 4 + 2)];
                f4.w = X[AFIDX(rb, fg, qq * 4 + 3)] + E[AFIDX(rb, fg, qq * 4 + 3)];
                *(float4*)(ho + c2 * 32 + qq * 4) = f4;
            }
        }
    }
}

// ---------------- node embedding ----------------------------------------------
__global__ __launch_bounds__(256, 1) void emb_k(
    const float* __restrict__ nodes, const float* __restrict__ wE,
    const float* __restrict__ bias, float* __restrict__ h)
{
    extern __shared__ float smf[];
    int tid = threadIdx.x, lane = tid & 31, wid = tid >> 5;
    int wm = wid & 3, wn = wid >> 2;
    int g = lane >> 2, tig = lane & 3;
    int pl4 = (g * 4 + (tig ^ fAg(g))) << 2;
    int base = blockIdx.x * 128;
    int r = tid >> 1, hh = tid & 1;
    if (tid < 128) smf[F_PAR + tid] = bias[tid];
    int nr = min(base + r, NNODES - 1);
    const float* src = nodes + (size_t)nr * 288;

    float C[2][8][4];
    ZERO_C();
    copy_w(smf + F_SW, wE, tid);
    stage_Af(smf + F_SG, src + hh * 16, r, hh);
    __syncthreads();
#pragma unroll 1
    for (int c = 0; c < 9; c++) {
        if (c < 8) {
            int cn = c + 1;
            copy_w(smf + F_SW + (cn & 1) * 4096, wE + cn * 4096, tid);
            stage_Af(smf + F_SG + (cn & 1) * 4096, src + cn * 32 + hh * 16, r, hh);
        }
        chunk_mma(smf + F_SG + (c & 1) * 4096, smf + F_SW + (c & 1) * 4096,
                  C, wm, wn, lane, pl4);
        __syncthreads();
    }
    write_XT(C, smf, wm, wn, lane, 0);
    __syncthreads();
    if (base + r < NNODES) {
        ROWBASE(r, rb, fg);
        float* ho = h + (size_t)(base + r) * DM + hh * 64;
#pragma unroll
        for (int c2 = 0; c2 < 2; c2++) {
            const float* X = smf + F_XT + (hh * 2 + c2) * 4096;
            const float* B = smf + F_PAR + hh * 64 + c2 * 32;
#pragma unroll
            for (int qq = 0; qq < 8; qq++) {
                float4 f4;
                f4.x = X[AFIDX(rb, fg, qq * 4 + 0)] + B[qq * 4 + 0];
                f4.y = X[AFIDX(rb, fg, qq * 4 + 1)] + B[qq * 4 + 1];
                f4.z = X[AFIDX(rb, fg, qq * 4 + 2)] + B[qq * 4 + 2];
                f4.w = X[AFIDX(rb, fg, qq * 4 + 3)] + B[qq * 4 + 3];
                *(float4*)(ho + c2 * 32 + qq * 4) = f4;
            }
        }
    }
}

// ---------------- output kernel ------------------------------------------------
__global__ __launch_bounds__(256, 1) void out_k(
    const float* __restrict__ h, const float* __restrict__ wO,
    const float* __restrict__ bias, const float* __restrict__ gg,
    const float* __restrict__ bb, const float* __restrict__ pw,
    const float* __restrict__ pb, float* __restrict__ out)
{
    extern __shared__ float smf[];
    int tid = threadIdx.x, lane = tid & 31, wid = tid >> 5;
    int wm = wid & 3, wn = wid >> 2;
    int g = lane >> 2, tig = lane & 3;
    int pl4 = (g * 4 + (tig ^ fAg(g))) << 2;
    int base = blockIdx.x * 128;
    int r = tid >> 1, hh = tid & 1;
    if (tid < 128) {
        smf[F_PAR + tid] = bias[tid];
        smf[F_PAR + 128 + tid] = gg[tid];
        smf[F_PAR + 256 + tid] = bb[tid];
    }
    int nr = min(base + r, NNODES - 1);
    const float* src = h + (size_t)nr * DM;

    float C[2][8][4];
    ZERO_C();
    copy_w(smf + F_SW, wO, tid);
    stage_Af(smf + F_SG, src + hh * 16, r, hh);
    __syncthreads();
#pragma unroll 1
    for (int c = 0; c < 4; c++) {
        if (c < 3) {
            int cn = c + 1;
            copy_w(smf + F_SW + (cn & 1) * 4096, wO + cn * 4096, tid);
            stage_Af(smf + F_SG + (cn & 1) * 4096, src + cn * 32 + hh * 16, r, hh);
        }
        chunk_mma(smf + F_SG + (c & 1) * 4096, smf + F_SW + (c & 1) * 4096,
                  C, wm, wn, lane, pl4);
        __syncthreads();
    }
    gelu_ln_ep(C, smf, wm, wn, lane, F_PAR, F_PAR + 128, F_PAR + 256);
    write_XT(C, smf, wm, wn, lane, 0);
    // projection weights into ET region
    float* sPw = smf + F_ET;
    for (int i = tid; i < 128 * PREDL; i += 256) sPw[i] = pw[i];
    if (tid < PREDL) smf[F_ET + 128 * PREDL + tid] = pb[tid];
    __syncthreads();

    if (base + r < NNODES) {
        ROWBASE(r, rb, fg);
        float acc[12];
#pragma unroll
        for (int j = 0; j < 12; j++) acc[j] = smf[F_ET + 128 * PREDL + hh * 12 + j];
#pragma unroll 1
        for (int ch = 0; ch < 4; ch++) {
            const float* X = smf + F_XT + ch * 4096;
#pragma unroll
            for (int j = 0; j < 32; j++) {
                float xv = X[AFIDX(rb, fg, j)];
                const float* pr = sPw + (ch * 32 + j) * PREDL + hh * 12;
#pragma unroll
                for (int o = 0; o < 12; o++) acc[o] = fmaf(xv, pr[o], acc[o]);
            }
        }
        float* op = out + (size_t)(base + r) * PREDL + hh * 12;
#pragma unroll
        for (int j = 0; j < 12; j++) op[j] = acc[j];
    }
}

// ---------------- small kernels -------------------------------------------------
__global__ void emb_edge_kernel(const float* __restrict__ edges,
                                const float* __restrict__ W,
                                const float* __restrict__ bias,
                                float* __restrict__ e)
{
    int idx = blockIdx.x * 256 + threadIdx.x;
    if (idx >= NEDGES * 32) return;
    int ei = idx >> 5, c4 = idx & 31;
    float x0 = edges[2 * ei], x1 = edges[2 * ei + 1];
    float4 w0 = *(const float4*)(W + c4 * 4);
    float4 w1 = *(const float4*)(W + DM + c4 * 4);
    float4 b  = *(const float4*)(bias + c4 * 4);
    float4 o;
    o.x = fmaf(x0, w0.x, fmaf(x1, w1.x, b.x));
    o.y = fmaf(x0, w0.y, fmaf(x1, w1.y, b.y));
    o.z = fmaf(x0, w0.z, fmaf(x1, w1.z, b.z));
    o.w = fmaf(x0, w0.w, fmaf(x1, w1.w, b.w));
    *(float4*)(e + (size_t)ei * DM + c4 * 4) = o;
}

__global__ void count_kernel(const int* __restrict__ receivers,
                             float* __restrict__ cnt)
{
    int i = blockIdx.x * 256 + threadIdx.x;
    if (i < NEDGES) atomicAdd(&cnt[receivers[i]], 1.0f);
}

// ---------------- launch ------------------------------------------------------
extern "C" void kernel_launch(void* const* d_in, const int* in_sizes, int n_in,
                              void* d_out, int out_size)
{
    const float* nodes        = (const float*)d_in[0];
    const float* edges        = (const float*)d_in[1];
    const int*   senders      = (const int*)d_in[2];
    const int*   receivers    = (const int*)d_in[3];
    const float* w_node_emb   = (const float*)d_in[4];
    const float* b_node_emb   = (const float*)d_in[5];
    const float* w_edge_emb   = (const float*)d_in[6];
    const float* b_edge_emb   = (const float*)d_in[7];
    const float* edge_proj_w  = (const float*)d_in[8];
    const float* edge_proj_b  = (const float*)d_in[9];
    const float* node_proj_w  = (const float*)d_in[10];
    const float* node_proj_b  = (const float*)d_in[11];
    const float* edge_mlp_w   = (const float*)d_in[12];
    const float* edge_mlp_b   = (const float*)d_in[13];
    const float* edge_ln_g    = (const float*)d_in[14];
    const float* edge_ln_b    = (const float*)d_in[15];
    const float* node_mlp_w   = (const float*)d_in[16];
    const float* node_mlp_b   = (const float*)d_in[17];
    const float* node_ln_g    = (const float*)d_in[18];
    const float* node_ln_b    = (const float*)d_in[19];
    const float* mlp_out_w    = (const float*)d_in[20];
    const float* mlp_out_b    = (const float*)d_in[21];
    const float* mlp_out_g    = (const float*)d_in[22];
    const float* mlp_out_beta = (const float*)d_in[23];
    const float* proj_w       = (const float*)d_in[24];
    const float* proj_b       = (const float*)d_in[25];
    float* out = (float*)d_out;

    float *h, *e, *agg, *cnt, *wt;
    cudaGetSymbolAddress((void**)&h,   g_h);
    cudaGetSymbolAddress((void**)&e,   g_e);
    cudaGetSymbolAddress((void**)&agg, g_agg);
    cudaGetSymbolAddress((void**)&cnt, g_cnt);
    cudaGetSymbolAddress((void**)&wt,  g_wt);

    cudaFuncSetAttribute(edge_k, cudaFuncAttributeMaxDynamicSharedMemorySize, SMEMB);
    cudaFuncSetAttribute(node_k, cudaFuncAttributeMaxDynamicSharedMemorySize, SMEMB);
    cudaFuncSetAttribute(emb_k,  cudaFuncAttributeMaxDynamicSharedMemorySize, SMEMB);
    cudaFuncSetAttribute(out_k,  cudaFuncAttributeMaxDynamicSharedMemorySize, SMEMB);

    // weight prep into fragment layout (cheap; graph-capturable)
    prep_w<<<24, 256>>>(edge_proj_w, wt + C_WPE * 4096);
    prep_w<<<16, 256>>>(node_proj_w, wt + C_WPN * 4096);
    prep_w<<<16, 256>>>(edge_mlp_w,  wt + C_WME * 4096);
    prep_w<<<16, 256>>>(node_mlp_w,  wt + C_WMN * 4096);
    prep_w<<<4,  256>>>(mlp_out_w,   wt + C_WOUT * 4096);
    prep_w<<<9,  256>>>(w_node_emb,  wt + C_WEMB * 4096);

    int nblk = (NNODES + 127) / 128;  // 157

    cudaMemsetAsync(cnt, 0, NNODES * sizeof(float));
    emb_k<<<nblk, 256, SMEMB>>>(nodes, wt + C_WEMB * 4096, b_node_emb, h);
    emb_edge_kernel<<<NEDGES * 32 / 256, 256>>>(edges, w_edge_emb, b_edge_emb, e);
    count_kernel<<<(NEDGES + 255) / 256, 256>>>(receivers, cnt);

    for (int l = 0; l < 2; l++) {
        cudaMemsetAsync(agg, 0, (size_t)NNODES * DM * sizeof(float));
        edge_k<<<NEDGES / 128, 256, SMEMB>>>(
            h, e, senders, receivers,
            wt + (C_WPE + l * 12) * 4096, edge_proj_b + l * 128,
            wt + (C_WME + (l * 2 + 0) * 4) * 4096, edge_mlp_b + (l * 2 + 0) * 128,
            edge_ln_g + (l * 2 + 0) * 128, edge_ln_b + (l * 2 + 0) * 128,
            wt + (C_WME + (l * 2 + 1) * 4) * 4096, edge_mlp_b + (l * 2 + 1) * 128,
            edge_ln_g + (l * 2 + 1) * 128, edge_ln_b + (l * 2 + 1) * 128,
            agg);
        node_k<<<nblk, 256, SMEMB>>>(
            h, agg, cnt,
            wt + (C_WPN + l * 8) * 4096, node_proj_b + l * 128,
            wt + (C_WMN + (l * 2 + 0) * 4) * 4096, node_mlp_b + (l * 2 + 0) * 128,
            node_ln_g + (l * 2 + 0) * 128, node_ln_b + (l * 2 + 0) * 128,
            wt + (C_WMN + (l * 2 + 1) * 4) * 4096, node_mlp_b + (l * 2 + 1) * 128,
            node_ln_g + (l * 2 + 1) * 128, node_ln_b + (l * 2 + 1) * 128);
    }
    out_k<<<nblk, 256, SMEMB>>>(h, wt + C_WOUT * 4096, mlp_out_b, mlp_out_g,
                                mlp_out_beta, proj_w, proj_b, out);
}

// round 6
// speedup vs baseline: 3.2682x; 1.0615x over previous
#include <cuda_runtime.h>
#include <cstdint>

#define NNODES 20000
#define NEDGES 320000
#define DM 128
#define PREDL 24

// ---------------- device scratch ----------------------------------------------
__device__ float g_h[NNODES * DM];
__device__ float g_e[(size_t)NEDGES * DM];
__device__ float g_agg[NNODES * DM];
__device__ float g_cnt[NNODES];
__device__ float g_wt[85 * 4096];     // fragment-layout weights (tf32-rounded)

// weight blob offsets (in 4096-float chunks)
#define C_WPE  0     // edge proj  2 x 12
#define C_WPN  24    // node proj  2 x 8
#define C_WME  40    // edge mlp   4 x 4
#define C_WMN  56    // node mlp   4 x 4
#define C_WOUT 72    // out mlp    4
#define C_WEMB 76    // node emb   9

// ---------------- smem float offsets -------------------------------------------
#define F_IDX 0                 // 256 ints (snd|rcv) or 128 inv floats
#define F_SUM 256               // 512 (4 warps per row)
#define F_SQ  768               // 512
#define F_PAR 1280              // up to 896 per-col params
#define F_SW  2176              // 2 x 4096 W double buffer
#define F_SG  (F_SW + 8192)     // 2 x 4096 gather double buffer
#define F_ET  (F_SG + 8192)     // 4 x 4096 persistent residual tile (exact f32)
#define F_XT  (F_ET + 16384)    // 4 x 4096 activation tile
#define SMEMB ((F_XT + 16384) * 4)   // 205312 bytes

// ---------------- helpers ------------------------------------------------------
__device__ __forceinline__ uint32_t tfr(float x) {
    uint32_t r;
    asm("cvt.rna.tf32.f32 %0, %1;" : "=r"(r) : "f"(x));
    return r;
}
__device__ __forceinline__ float tff(float x) { return __uint_as_float(tfr(x)); }

__device__ __forceinline__ uint32_t smem_u32(const void* p) {
    uint32_t a;
    asm("{ .reg .u64 t; cvta.to.shared.u64 t, %1; cvt.u32.u64 %0, t; }"
        : "=r"(a) : "l"(p));
    return a;
}

__device__ __forceinline__ void mma8(float c[4], uint32_t a0, uint32_t a1,
                                     uint32_t a2, uint32_t a3,
                                     uint32_t b0, uint32_t b1) {
    asm volatile(
        "mma.sync.aligned.m16n8k8.row.col.f32.tf32.tf32.f32 "
        "{%0,%1,%2,%3}, {%4,%5,%6,%7}, {%8,%9}, {%0,%1,%2,%3};"
        : "+f"(c[0]), "+f"(c[1]), "+f"(c[2]), "+f"(c[3])
        : "r"(a0), "r"(a1), "r"(a2), "r"(a3), "r"(b0), "r"(b1));
}

__device__ __forceinline__ float geluf(float x) {
    float x3 = x * x * x;
    return 0.5f * x * (1.0f + tanhf(0.7978845608028654f * (x + 0.044715f * x3)));
}

__device__ __forceinline__ int fAg(int g) { return (g ^ (g >> 2)) & 3; }

// A-fragment index within a 4096-float chunk, for (row 0..127, k_local 0..31)
__device__ __forceinline__ int aidx(int row, int kl) {
    int wm = row >> 5, mm = (row >> 4) & 1, r8 = (row >> 3) & 1, g = row & 7;
    int kk = kl >> 3, k4 = (kl >> 2) & 1, tig = kl & 3;
    return (((kk * 4 + wm) * 2 + mm) << 7) + ((g * 4 + (tig ^ fAg(g))) << 2)
           + r8 + (k4 << 1);
}
// B-fragment index (16-warp layout): wn = n>>5 (4 warps x 32 cols)
__device__ __forceinline__ int bidx(int kl, int n) {
    int kk = kl >> 3, k4 = (kl >> 2) & 1, tig = kl & 3;
    int wn = n >> 5, ntp = (n >> 4) & 1, ntb = (n >> 3) & 1, gq = n & 7;
    return (((kk * 4 + wn) * 2 + ntp) << 7) + ((gq * 4 + tig) << 2)
           + ntb * 2 + k4;
}

// cp.async 16B helpers
#define CP16(daddr, src) asm volatile( \
    "cp.async.cg.shared.global [%0], [%1], 16;" :: "r"(daddr), "l"(src))
#define CP_COMMIT() asm volatile("cp.async.commit_group;" ::: "memory")
#define CP_WAIT0()  asm volatile("cp.async.wait_group 0;" ::: "memory")

// async-stage one 16KB pre-fragmented W chunk (512 threads x 32B)
__device__ __forceinline__ void copy_w_async(uint32_t dsts,
                                             const float* __restrict__ src,
                                             int tid) {
    CP16(dsts + tid * 16, src + tid * 4);
    CP16(dsts + (tid + 512) * 16, src + (tid + 512) * 4);
}

// one 32-wide K chunk; warp covers 32 rows x 32 cols
__device__ __forceinline__ void chunk_mma(const float* __restrict__ sA,
                                          const float* __restrict__ sW,
                                          float C[2][4][4], int wm, int wn,
                                          int lane, int pl4) {
#pragma unroll
    for (int kk = 0; kk < 4; kk++) {
        float4 b0 = *(const float4*)(sW + (((kk * 4 + wn) * 2 + 0) << 7)
                                     + (lane << 2));
        float4 b1 = *(const float4*)(sW + (((kk * 4 + wn) * 2 + 1) << 7)
                                     + (lane << 2));
#pragma unroll
        for (int mm = 0; mm < 2; mm++) {
            float4 av = *(const float4*)(sA + (((kk * 4 + wm) * 2 + mm) << 7) + pl4);
            uint32_t a0 = __float_as_uint(av.x), a1 = __float_as_uint(av.y);
            uint32_t a2 = __float_as_uint(av.z), a3 = __float_as_uint(av.w);
            mma8(C[mm][0], a0, a1, a2, a3,
                 __float_as_uint(b0.x), __float_as_uint(b0.y));
            mma8(C[mm][1], a0, a1, a2, a3,
                 __float_as_uint(b0.z), __float_as_uint(b0.w));
            mma8(C[mm][2], a0, a1, a2, a3,
                 __float_as_uint(b1.x), __float_as_uint(b1.y));
            mma8(C[mm][3], a0, a1, a2, a3,
                 __float_as_uint(b1.z), __float_as_uint(b1.w));
        }
    }
}

// stage 8 gathered floats (row r, kl = q4*8..+7) into A-frag chunk, tf32
__device__ __forceinline__ void stage_Af8(float* chunk, const float* __restrict__ src,
                                          int r, int q4) {
    float4 v0 = *(const float4*)(src);
    float4 v1 = *(const float4*)(src + 4);
    chunk[aidx(r, q4 * 8 + 0)] = tff(v0.x);
    chunk[aidx(r, q4 * 8 + 1)] = tff(v0.y);
    chunk[aidx(r, q4 * 8 + 2)] = tff(v0.z);
    chunk[aidx(r, q4 * 8 + 3)] = tff(v0.w);
    chunk[aidx(r, q4 * 8 + 4)] = tff(v1.x);
    chunk[aidx(r, q4 * 8 + 5)] = tff(v1.y);
    chunk[aidx(r, q4 * 8 + 6)] = tff(v1.z);
    chunk[aidx(r, q4 * 8 + 7)] = tff(v1.w);
}
__device__ __forceinline__ void stage_Af8s(float* chunk, const float* __restrict__ src,
                                           int r, int q4, float sc) {
    float4 v0 = *(const float4*)(src);
    float4 v1 = *(const float4*)(src + 4);
    chunk[aidx(r, q4 * 8 + 0)] = tff(v0.x * sc);
    chunk[aidx(r, q4 * 8 + 1)] = tff(v0.y * sc);
    chunk[aidx(r, q4 * 8 + 2)] = tff(v0.z * sc);
    chunk[aidx(r, q4 * 8 + 3)] = tff(v0.w * sc);
    chunk[aidx(r, q4 * 8 + 4)] = tff(v1.x * sc);
    chunk[aidx(r, q4 * 8 + 5)] = tff(v1.y * sc);
    chunk[aidx(r, q4 * 8 + 6)] = tff(v1.z * sc);
    chunk[aidx(r, q4 * 8 + 7)] = tff(v1.w * sc);
}

// stage 32 cols (chunk q4) of a 128-wide row EXACT into A-frag chunk
__device__ __forceinline__ void stage_E32(float* chunk, const float* __restrict__ src,
                                          int r) {
#pragma unroll
    for (int i = 0; i < 8; i++) {
        float4 v = *(const float4*)(src + i * 4);
        chunk[aidx(r, i * 4 + 0)] = v.x;
        chunk[aidx(r, i * 4 + 1)] = v.y;
        chunk[aidx(r, i * 4 + 2)] = v.z;
        chunk[aidx(r, i * 4 + 3)] = v.w;
    }
}

// GEMM1 epilogue: D + bias -> XT (tf32)
__device__ __forceinline__ void ep_bias_to_XT(float C[2][4][4], float* smf,
                                              int wm, int wn, int lane, int pbias) {
    int g = lane >> 2, q = lane & 3;
#pragma unroll
    for (int mm = 0; mm < 2; mm++)
#pragma unroll
        for (int hx = 0; hx < 2; hx++) {
            int row = wm * 32 + mm * 16 + hx * 8 + g;
#pragma unroll
            for (int nt = 0; nt < 4; nt++)
#pragma unroll
                for (int s = 0; s < 2; s++) {
                    int col = wn * 32 + nt * 8 + q * 2 + s;
                    smf[F_XT + (col >> 5) * 4096 + aidx(row, col & 31)] =
                        tff(C[mm][nt][hx * 2 + s] + smf[pbias + col]);
                }
        }
}

// post-LN write to XT (cvt: 1 = tf32 round for next GEMM, 0 = exact)
__device__ __forceinline__ void write_XT(float C[2][4][4], float* smf,
                                         int wm, int wn, int lane, int cvt) {
    int g = lane >> 2, q = lane & 3;
#pragma unroll
    for (int mm = 0; mm < 2; mm++)
#pragma unroll
        for (int hx = 0; hx < 2; hx++) {
            int row = wm * 32 + mm * 16 + hx * 8 + g;
#pragma unroll
            for (int nt = 0; nt < 4; nt++)
#pragma unroll
                for (int s = 0; s < 2; s++) {
                    int col = wn * 32 + nt * 8 + q * 2 + s;
                    float v = C[mm][nt][hx * 2 + s];
                    smf[F_XT + (col >> 5) * 4096 + aidx(row, col & 31)] =
                        cvt ? tff(v) : v;
                }
        }
}

// gelu + LayerNorm over 128-wide rows (4 warps per row combine via smem)
__device__ __forceinline__ void gelu_ln_ep(float C[2][4][4], float* smf,
                                           int wm, int wn, int lane,
                                           int pb, int pg, int pbe) {
    int g = lane >> 2, q = lane & 3;
    float* sSum = smf + F_SUM;
    float* sSq  = smf + F_SQ;
#pragma unroll
    for (int mm = 0; mm < 2; mm++)
#pragma unroll
        for (int hx = 0; hx < 2; hx++) {
            float ps = 0.f, pq = 0.f;
#pragma unroll
            for (int nt = 0; nt < 4; nt++)
#pragma unroll
                for (int s = 0; s < 2; s++) {
                    int col = wn * 32 + nt * 8 + q * 2 + s;
                    float v = geluf(C[mm][nt][hx * 2 + s] + smf[pb + col]);
                    C[mm][nt][hx * 2 + s] = v;
                    ps += v; pq += v * v;
                }
            ps += __shfl_xor_sync(0xffffffffu, ps, 1);
            ps += __shfl_xor_sync(0xffffffffu, ps, 2);
            pq += __shfl_xor_sync(0xffffffffu, pq, 1);
            pq += __shfl_xor_sync(0xffffffffu, pq, 2);
            if (q == 0) {
                int row = wm * 32 + mm * 16 + hx * 8 + g;
                sSum[row * 4 + wn] = ps;
                sSq[row * 4 + wn]  = pq;
            }
        }
    __syncthreads();
#pragma unroll
    for (int mm = 0; mm < 2; mm++)
#pragma unroll
        for (int hx = 0; hx < 2; hx++) {
            int row = wm * 32 + mm * 16 + hx * 8 + g;
            float m = (sSum[row * 4] + sSum[row * 4 + 1]
                       + sSum[row * 4 + 2] + sSum[row * 4 + 3]) * (1.0f / 128.0f);
            float qv = (sSq[row * 4] + sSq[row * 4 + 1]
                        + sSq[row * 4 + 2] + sSq[row * 4 + 3]) * (1.0f / 128.0f);
            float rs = rsqrtf(qv - m * m + 1e-5f);
#pragma unroll
            for (int nt = 0; nt < 4; nt++)
#pragma unroll
                for (int s = 0; s < 2; s++) {
                    int col = wn * 32 + nt * 8 + q * 2 + s;
                    C[mm][nt][hx * 2 + s] =
                        (C[mm][nt][hx * 2 + s] - m) * rs * smf[pg + col] + smf[pbe + col];
                }
        }
}

#define ZERO_C() do { \
    _Pragma("unroll") for (int _m = 0; _m < 2; _m++) \
    _Pragma("unroll") for (int _n = 0; _n < 4; _n++) \
    _Pragma("unroll") for (int _s = 0; _s < 4; _s++) C[_m][_n][_s] = 0.f; } while (0)

// K=128 GEMM with A = XT chunks, W async-streamed double-buffered
__device__ __forceinline__ void gemm_XT(float* smf, uint32_t swb,
                                        const float* __restrict__ W,
                                        float C[2][4][4], int tid,
                                        int wm, int wn, int lane, int pl4) {
    copy_w_async(swb, W, tid); CP_COMMIT();
    CP_WAIT0(); __syncthreads();
#pragma unroll 1
    for (int c = 0; c < 4; c++) {
        if (c < 3) {
            copy_w_async(swb + ((c + 1) & 1) * 16384, W + (c + 1) * 4096, tid);
            CP_COMMIT();
        }
        chunk_mma(smf + F_XT + c * 4096, smf + F_SW + (c & 1) * 4096,
                  C, wm, wn, lane, pl4);
        CP_WAIT0();
        __syncthreads();
    }
}

// row-major readback base for A-frag reads
#define ROWBASE(r, rb, fg) \
    int rb = ((((r) >> 5) * 2 + (((r) >> 4) & 1)) << 7) + (((r) & 7) << 4) \
             + (((r) >> 3) & 1); \
    int fg = fAg((r) & 7)
#define AFIDX(rb, fg, j) \
    (((j) >> 3) * 1024 + (rb) + ((((j) & 3) ^ (fg)) << 2) + ((((j) >> 2) & 1) << 1))

#define RED4(p, f4) asm volatile( \
    "red.global.add.v4.f32 [%0], {%1,%2,%3,%4};" \
    :: "l"(p), "f"((f4).x), "f"((f4).y), "f"((f4).z), "f"((f4).w) : "memory")

// ---------------- weight prep: W[K,128] -> B-frag chunks (tf32) ---------------
__global__ void prep_w(const float* __restrict__ W, float* __restrict__ dst) {
    int c = blockIdx.x, tid = threadIdx.x;
    int kl = tid >> 3, n0 = (tid & 7) * 16;
#pragma unroll
    for (int j = 0; j < 16; j++) {
        int n = n0 + j;
        dst[c * 4096 + bidx(kl, n)] = tff(W[(c * 32 + kl) * 128 + n]);
    }
}

// ---------------- edge kernel --------------------------------------------------
__global__ __launch_bounds__(512, 1) void edge_k(
    const float* __restrict__ h, float* __restrict__ e,
    const int* __restrict__ snd, const int* __restrict__ rcv,
    const float* __restrict__ wP, const float* __restrict__ bp,
    const float* __restrict__ wM0, const float* __restrict__ b0,
    const float* __restrict__ g0, const float* __restrict__ be0,
    const float* __restrict__ wM1, const float* __restrict__ b1,
    const float* __restrict__ g1, const float* __restrict__ be1,
    float* __restrict__ agg)
{
    extern __shared__ float smf[];
    uint32_t swb = smem_u32(smf) + F_SW * 4;
    int tid = threadIdx.x, lane = tid & 31, wid = tid >> 5;
    int wm = wid & 3, wn = wid >> 2;
    int g = lane >> 2, tig = lane & 3;
    int pl4 = (g * 4 + (tig ^ fAg(g))) << 2;
    int base = blockIdx.x * 128;
    int r = tid >> 2, q4 = tid & 3;
    int* sI = (int*)smf;
    if (tid < 128) sI[tid] = snd[base + tid];
    else if (tid < 256) sI[tid] = rcv[base + tid - 128];
    if (tid < 128) {
        float* p = smf + F_PAR;
        p[tid] = bp[tid];        p[128 + tid] = b0[tid];
        p[256 + tid] = g0[tid];  p[384 + tid] = be0[tid];
        p[512 + tid] = b1[tid];  p[640 + tid] = g1[tid];
        p[768 + tid] = be1[tid];
    }
    stage_E32(smf + F_ET + q4 * 4096, e + (size_t)(base + r) * DM + q4 * 32, r);

    float C[2][4][4];
    ZERO_C();
    // GEMM1: K=384 (chunks 0-3 = e tile exact, 4-11 gathered h[snd]/h[rcv])
    copy_w_async(swb, wP, tid); CP_COMMIT();
    CP_WAIT0(); __syncthreads();
#pragma unroll 1
    for (int c = 0; c < 12; c++) {
        if (c < 11) {
            int cn = c + 1;
            copy_w_async(swb + (cn & 1) * 16384, wP + cn * 4096, tid); CP_COMMIT();
            if (cn >= 4) {
                int idx = sI[(cn < 8 ? 0 : 128) + r];
                stage_Af8(smf + F_SG + (cn & 1) * 4096,
                          h + (size_t)idx * DM + ((cn & 3) << 5) + q4 * 8, r, q4);
            }
        }
        const float* As = (c < 4) ? smf + F_ET + c * 4096
                                  : smf + F_SG + (c & 1) * 4096;
        chunk_mma(As, smf + F_SW + (c & 1) * 4096, C, wm, wn, lane, pl4);
        CP_WAIT0();
        __syncthreads();
    }
    ep_bias_to_XT(C, smf, wm, wn, lane, F_PAR);
    ZERO_C();
    gemm_XT(smf, swb, wM0, C, tid, wm, wn, lane, pl4);     // MLP layer 0
    gelu_ln_ep(C, smf, wm, wn, lane, F_PAR + 128, F_PAR + 256, F_PAR + 384);
    write_XT(C, smf, wm, wn, lane, 1);
    ZERO_C();
    gemm_XT(smf, swb, wM1, C, tid, wm, wn, lane, pl4);     // MLP layer 1
    gelu_ln_ep(C, smf, wm, wn, lane, F_PAR + 512, F_PAR + 640, F_PAR + 768);
    write_XT(C, smf, wm, wn, lane, 0);                     // exact
    __syncthreads();

    // residual + store + vector scatter (thread owns row r, chunk q4)
    {
        ROWBASE(r, rb, fg);
        const float* X = smf + F_XT + q4 * 4096;
        const float* E = smf + F_ET + q4 * 4096;
        float* eo = e + (size_t)(base + r) * DM + q4 * 32;
        float* ag = agg + (size_t)sI[128 + r] * DM + q4 * 32;
#pragma unroll
        for (int qq = 0; qq < 8; qq++) {
            float4 f4;
            f4.x = X[AFIDX(rb, fg, qq * 4 + 0)] + E[AFIDX(rb, fg, qq * 4 + 0)];
            f4.y = X[AFIDX(rb, fg, qq * 4 + 1)] + E[AFIDX(rb, fg, qq * 4 + 1)];
            f4.z = X[AFIDX(rb, fg, qq * 4 + 2)] + E[AFIDX(rb, fg, qq * 4 + 2)];
            f4.w = X[AFIDX(rb, fg, qq * 4 + 3)] + E[AFIDX(rb, fg, qq * 4 + 3)];
            *(float4*)(eo + qq * 4) = f4;
            RED4(ag + qq * 4, f4);
        }
    }
}

// ---------------- node kernel --------------------------------------------------
__global__ __launch_bounds__(512, 1) void node_k(
    float* __restrict__ h, const float* __restrict__ agg,
    const float* __restrict__ cnt,
    const float* __restrict__ wP, const float* __restrict__ bp,
    const float* __restrict__ wM0, const float* __restrict__ b0,
    const float* __restrict__ g0, const float* __restrict__ be0,
    const float* __restrict__ wM1, const float* __restrict__ b1,
    const float* __restrict__ g1, const float* __restrict__ be1)
{
    extern __shared__ float smf[];
    uint32_t swb = smem_u32(smf) + F_SW * 4;
    int tid = threadIdx.x, lane = tid & 31, wid = tid >> 5;
    int wm = wid & 3, wn = wid >> 2;
    int g = lane >> 2, tig = lane & 3;
    int pl4 = (g * 4 + (tig ^ fAg(g))) << 2;
    int base = blockIdx.x * 128;
    int r = tid >> 2, q4 = tid & 3;
    if (tid < 128) {
        int n = min(base + tid, NNODES - 1);
        smf[tid] = 1.0f / fmaxf(cnt[n], 1.0f);
        float* p = smf + F_PAR;
        p[tid] = bp[tid];        p[128 + tid] = b0[tid];
        p[256 + tid] = g0[tid];  p[384 + tid] = be0[tid];
        p[512 + tid] = b1[tid];  p[640 + tid] = g1[tid];
        p[768 + tid] = be1[tid];
    }
    int nr = min(base + r, NNODES - 1);
    stage_E32(smf + F_ET + q4 * 4096, h + (size_t)nr * DM + q4 * 32, r);

    float C[2][4][4];
    ZERO_C();
    copy_w_async(swb, wP, tid); CP_COMMIT();
    CP_WAIT0(); __syncthreads();
#pragma unroll 1
    for (int c = 0; c < 8; c++) {
        if (c < 7) {
            int cn = c + 1;
            copy_w_async(swb + (cn & 1) * 16384, wP + cn * 4096, tid); CP_COMMIT();
            if (cn >= 4)
                stage_Af8s(smf + F_SG + (cn & 1) * 4096,
                           agg + (size_t)nr * DM + ((cn & 3) << 5) + q4 * 8,
                           r, q4, smf[r]);
        }
        const float* As = (c < 4) ? smf + F_ET + c * 4096
                                  : smf + F_SG + (c & 1) * 4096;
        chunk_mma(As, smf + F_SW + (c & 1) * 4096, C, wm, wn, lane, pl4);
        CP_WAIT0();
        __syncthreads();
    }
    ep_bias_to_XT(C, smf, wm, wn, lane, F_PAR);
    ZERO_C();
    gemm_XT(smf, swb, wM0, C, tid, wm, wn, lane, pl4);
    gelu_ln_ep(C, smf, wm, wn, lane, F_PAR + 128, F_PAR + 256, F_PAR + 384);
    write_XT(C, smf, wm, wn, lane, 1);
    ZERO_C();
    gemm_XT(smf, swb, wM1, C, tid, wm, wn, lane, pl4);
    gelu_ln_ep(C, smf, wm, wn, lane, F_PAR + 512, F_PAR + 640, F_PAR + 768);
    write_XT(C, smf, wm, wn, lane, 0);
    __syncthreads();

    if (base + r < NNODES) {
        ROWBASE(r, rb, fg);
        const float* X = smf + F_XT + q4 * 4096;
        const float* E = smf + F_ET + q4 * 4096;
        float* ho = h + (size_t)(base + r) * DM + q4 * 32;
#pragma unroll
        for (int qq = 0; qq < 8; qq++) {
            float4 f4;
            f4.x = X[AFIDX(rb, fg, qq * 4 + 0)] + E[AFIDX(rb, fg, qq * 4 + 0)];
            f4.y = X[AFIDX(rb, fg, qq * 4 + 1)] + E[AFIDX(rb, fg, qq * 4 + 1)];
            f4.z = X[AFIDX(rb, fg, qq * 4 + 2)] + E[AFIDX(rb, fg, qq * 4 + 2)];
            f4.w = X[AFIDX(rb, fg, qq * 4 + 3)] + E[AFIDX(rb, fg, qq * 4 + 3)];
            *(float4*)(ho + qq * 4) = f4;
        }
    }
}

// ---------------- node embedding ----------------------------------------------
__global__ __launch_bounds__(512, 1) void emb_k(
    const float* __restrict__ nodes, const float* __restrict__ wE,
    const float* __restrict__ bias, float* __restrict__ h)
{
    extern __shared__ float smf[];
    uint32_t swb = smem_u32(smf) + F_SW * 4;
    int tid = threadIdx.x, lane = tid & 31, wid = tid >> 5;
    int wm = wid & 3, wn = wid >> 2;
    int g = lane >> 2, tig = lane & 3;
    int pl4 = (g * 4 + (tig ^ fAg(g))) << 2;
    int base = blockIdx.x * 128;
    int r = tid >> 2, q4 = tid & 3;
    if (tid < 128) smf[F_PAR + tid] = bias[tid];
    int nr = min(base + r, NNODES - 1);
    const float* src = nodes + (size_t)nr * 288;

    float C[2][4][4];
    ZERO_C();
    copy_w_async(swb, wE, tid); CP_COMMIT();
    stage_Af8(smf + F_SG, src + q4 * 8, r, q4);
    CP_WAIT0(); __syncthreads();
#pragma unroll 1
    for (int c = 0; c < 9; c++) {
        if (c < 8) {
            int cn = c + 1;
            copy_w_async(swb + (cn & 1) * 16384, wE + cn * 4096, tid); CP_COMMIT();
            stage_Af8(smf + F_SG + (cn & 1) * 4096, src + cn * 32 + q4 * 8, r, q4);
        }
        chunk_mma(smf + F_SG + (c & 1) * 4096, smf + F_SW + (c & 1) * 4096,
                  C, wm, wn, lane, pl4);
        CP_WAIT0();
        __syncthreads();
    }
    write_XT(C, smf, wm, wn, lane, 0);
    __syncthreads();
    if (base + r < NNODES) {
        ROWBASE(r, rb, fg);
        const float* X = smf + F_XT + q4 * 4096;
        const float* B = smf + F_PAR + q4 * 32;
        float* ho = h + (size_t)(base + r) * DM + q4 * 32;
#pragma unroll
        for (int qq = 0; qq < 8; qq++) {
            float4 f4;
            f4.x = X[AFIDX(rb, fg, qq * 4 + 0)] + B[qq * 4 + 0];
            f4.y = X[AFIDX(rb, fg, qq * 4 + 1)] + B[qq * 4 + 1];
            f4.z = X[AFIDX(rb, fg, qq * 4 + 2)] + B[qq * 4 + 2];
            f4.w = X[AFIDX(rb, fg, qq * 4 + 3)] + B[qq * 4 + 3];
            *(float4*)(ho + qq * 4) = f4;
        }
    }
}

// ---------------- output kernel ------------------------------------------------
__global__ __launch_bounds__(512, 1) void out_k(
    const float* __restrict__ h, const float* __restrict__ wO,
    const float* __restrict__ bias, const float* __restrict__ gg,
    const float* __restrict__ bb, const float* __restrict__ pw,
    const float* __restrict__ pb, float* __restrict__ out)
{
    extern __shared__ float smf[];
    uint32_t swb = smem_u32(smf) + F_SW * 4;
    int tid = threadIdx.x, lane = tid & 31, wid = tid >> 5;
    int wm = wid & 3, wn = wid >> 2;
    int g = lane >> 2, tig = lane & 3;
    int pl4 = (g * 4 + (tig ^ fAg(g))) << 2;
    int base = blockIdx.x * 128;
    int r = tid >> 2, q4 = tid & 3;
    if (tid < 128) {
        smf[F_PAR + tid] = bias[tid];
        smf[F_PAR + 128 + tid] = gg[tid];
        smf[F_PAR + 256 + tid] = bb[tid];
    }
    int nr = min(base + r, NNODES - 1);
    const float* src = h + (size_t)nr * DM;

    float C[2][4][4];
    ZERO_C();
    copy_w_async(swb, wO, tid); CP_COMMIT();
    stage_Af8(smf + F_SG, src + q4 * 8, r, q4);
    CP_WAIT0(); __syncthreads();
#pragma unroll 1
    for (int c = 0; c < 4; c++) {
        if (c < 3) {
            int cn = c + 1;
            copy_w_async(swb + (cn & 1) * 16384, wO + cn * 4096, tid); CP_COMMIT();
            stage_Af8(smf + F_SG + (cn & 1) * 4096, src + cn * 32 + q4 * 8, r, q4);
        }
        chunk_mma(smf + F_SG + (c & 1) * 4096, smf + F_SW + (c & 1) * 4096,
                  C, wm, wn, lane, pl4);
        CP_WAIT0();
        __syncthreads();
    }
    gelu_ln_ep(C, smf, wm, wn, lane, F_PAR, F_PAR + 128, F_PAR + 256);
    write_XT(C, smf, wm, wn, lane, 0);
    // projection weights into ET region
    float* sPw = smf + F_ET;
    for (int i = tid; i < 128 * PREDL; i += 512) sPw[i] = pw[i];
    if (tid < PREDL) smf[F_ET + 128 * PREDL + tid] = pb[tid];
    __syncthreads();

    if (base + r < NNODES) {
        ROWBASE(r, rb, fg);
        float acc[6];
#pragma unroll
        for (int j = 0; j < 6; j++) acc[j] = smf[F_ET + 128 * PREDL + q4 * 6 + j];
#pragma unroll 1
        for (int ch = 0; ch < 4; ch++) {
            const float* X = smf + F_XT + ch * 4096;
#pragma unroll
            for (int j = 0; j < 32; j++) {
                float xv = X[AFIDX(rb, fg, j)];
                const float* pr = sPw + (ch * 32 + j) * PREDL + q4 * 6;
#pragma unroll
                for (int o = 0; o < 6; o++) acc[o] = fmaf(xv, pr[o], acc[o]);
            }
        }
        float* op = out + (size_t)(base + r) * PREDL + q4 * 6;
#pragma unroll
        for (int j = 0; j < 6; j++) op[j] = acc[j];
    }
}

// ---------------- small kernels -------------------------------------------------
__global__ void emb_edge_kernel(const float* __restrict__ edges,
                                const float* __restrict__ W,
                                const float* __restrict__ bias,
                                float* __restrict__ e)
{
    int idx = blockIdx.x * 256 + threadIdx.x;
    if (idx >= NEDGES * 32) return;
    int ei = idx >> 5, c4 = idx & 31;
    float x0 = edges[2 * ei], x1 = edges[2 * ei + 1];
    float4 w0 = *(const float4*)(W + c4 * 4);
    float4 w1 = *(const float4*)(W + DM + c4 * 4);
    float4 b  = *(const float4*)(bias + c4 * 4);
    float4 o;
    o.x = fmaf(x0, w0.x, fmaf(x1, w1.x, b.x));
    o.y = fmaf(x0, w0.y, fmaf(x1, w1.y, b.y));
    o.z = fmaf(x0, w0.z, fmaf(x1, w1.z, b.z));
    o.w = fmaf(x0, w0.w, fmaf(x1, w1.w, b.w));
    *(float4*)(e + (size_t)ei * DM + c4 * 4) = o;
}

__global__ void count_kernel(const int* __restrict__ receivers,
                             float* __restrict__ cnt)
{
    int i = blockIdx.x * 256 + threadIdx.x;
    if (i < NEDGES) atomicAdd(&cnt[receivers[i]], 1.0f);
}

// ---------------- launch ------------------------------------------------------
extern "C" void kernel_launch(void* const* d_in, const int* in_sizes, int n_in,
                              void* d_out, int out_size)
{
    const float* nodes        = (const float*)d_in[0];
    const float* edges        = (const float*)d_in[1];
    const int*   senders      = (const int*)d_in[2];
    const int*   receivers    = (const int*)d_in[3];
    const float* w_node_emb   = (const float*)d_in[4];
    const float* b_node_emb   = (const float*)d_in[5];
    const float* w_edge_emb   = (const float*)d_in[6];
    const float* b_edge_emb   = (const float*)d_in[7];
    const float* edge_proj_w  = (const float*)d_in[8];
    const float* edge_proj_b  = (const float*)d_in[9];
    const float* node_proj_w  = (const float*)d_in[10];
    const float* node_proj_b  = (const float*)d_in[11];
    const float* edge_mlp_w   = (const float*)d_in[12];
    const float* edge_mlp_b   = (const float*)d_in[13];
    const float* edge_ln_g    = (const float*)d_in[14];
    const float* edge_ln_b    = (const float*)d_in[15];
    const float* node_mlp_w   = (const float*)d_in[16];
    const float* node_mlp_b   = (const float*)d_in[17];
    const float* node_ln_g    = (const float*)d_in[18];
    const float* node_ln_b    = (const float*)d_in[19];
    const float* mlp_out_w    = (const float*)d_in[20];
    const float* mlp_out_b    = (const float*)d_in[21];
    const float* mlp_out_g    = (const float*)d_in[22];
    const float* mlp_out_beta = (const float*)d_in[23];
    const float* proj_w       = (const float*)d_in[24];
    const float* proj_b       = (const float*)d_in[25];
    float* out = (float*)d_out;

    float *h, *e, *agg, *cnt, *wt;
    cudaGetSymbolAddress((void**)&h,   g_h);
    cudaGetSymbolAddress((void**)&e,   g_e);
    cudaGetSymbolAddress((void**)&agg, g_agg);
    cudaGetSymbolAddress((void**)&cnt, g_cnt);
    cudaGetSymbolAddress((void**)&wt,  g_wt);

    cudaFuncSetAttribute(edge_k, cudaFuncAttributeMaxDynamicSharedMemorySize, SMEMB);
    cudaFuncSetAttribute(node_k, cudaFuncAttributeMaxDynamicSharedMemorySize, SMEMB);
    cudaFuncSetAttribute(emb_k,  cudaFuncAttributeMaxDynamicSharedMemorySize, SMEMB);
    cudaFuncSetAttribute(out_k,  cudaFuncAttributeMaxDynamicSharedMemorySize, SMEMB);

    // weight prep into fragment layout
    prep_w<<<24, 256>>>(edge_proj_w, wt + C_WPE * 4096);
    prep_w<<<16, 256>>>(node_proj_w, wt + C_WPN * 4096);
    prep_w<<<16, 256>>>(edge_mlp_w,  wt + C_WME * 4096);
    prep_w<<<16, 256>>>(node_mlp_w,  wt + C_WMN * 4096);
    prep_w<<<4,  256>>>(mlp_out_w,   wt + C_WOUT * 4096);
    prep_w<<<9,  256>>>(w_node_emb,  wt + C_WEMB * 4096);

    int nblk = (NNODES + 127) / 128;  // 157

    cudaMemsetAsync(cnt, 0, NNODES * sizeof(float));
    emb_k<<<nblk, 512, SMEMB>>>(nodes, wt + C_WEMB * 4096, b_node_emb, h);
    emb_edge_kernel<<<NEDGES * 32 / 256, 256>>>(edges, w_edge_emb, b_edge_emb, e);
    count_kernel<<<(NEDGES + 255) / 256, 256>>>(receivers, cnt);

    for (int l = 0; l < 2; l++) {
        cudaMemsetAsync(agg, 0, (size_t)NNODES * DM * sizeof(float));
        edge_k<<<NEDGES / 128, 512, SMEMB>>>(
            h, e, senders, receivers,
            wt + (C_WPE + l * 12) * 4096, edge_proj_b + l * 128,
            wt + (C_WME + (l * 2 + 0) * 4) * 4096, edge_mlp_b + (l * 2 + 0) * 128,
            edge_ln_g + (l * 2 + 0) * 128, edge_ln_b + (l * 2 + 0) * 128,
            wt + (C_WME + (l * 2 + 1) * 4) * 4096, edge_mlp_b + (l * 2 + 1) * 128,
            edge_ln_g + (l * 2 + 1) * 128, edge_ln_b + (l * 2 + 1) * 128,
            agg);
        node_k<<<nblk, 512, SMEMB>>>(
            h, agg, cnt,
            wt + (C_WPN + l * 8) * 4096, node_proj_b + l * 128,
            wt + (C_WMN + (l * 2 + 0) * 4) * 4096, node_mlp_b + (l * 2 + 0) * 128,
            node_ln_g + (l * 2 + 0) * 128, node_ln_b + (l * 2 + 0) * 128,
            wt + (C_WMN + (l * 2 + 1) * 4) * 4096, node_mlp_b + (l * 2 + 1) * 128,
            node_ln_g + (l * 2 + 1) * 128, node_ln_b + (l * 2 + 1) * 128);
    }
    out_k<<<nblk, 512, SMEMB>>>(h, wt + C_WOUT * 4096, mlp_out_b, mlp_out_g,
                                mlp_out_beta, proj_w, proj_b, out);
}